// round 10
// baseline (speedup 1.0000x reference)
#include <cuda_runtime.h>
#include <cuda_bf16.h>
#include <math.h>
#include <stdint.h>

// ---------------- static problem shape ----------------
#define BATCH 32
#define IMGH  56
#define IMGW  56
#define CCH   192
#define LLEN  (IMGH*IMGW)        // 3136
#define NHEAD 6
#define HDIM  32
#define WSZ   7
#define SHIFT_ 3
#define LW    49
#define NWIN  64
#define NWTOT (BATCH*NWIN)       // 2048
#define MTOK  (BATCH*LLEN)       // 100352
#define QKSCALE 13.856406460551018f

// bf16 weight buffer offsets (elements)
#define WB_QKV  0
#define WB_PROJ (WB_QKV + 3*CCH*CCH)
#define WB_FC1  (WB_PROJ + CCH*CCH)
#define WB_FC2  (WB_FC1 + 4*CCH*CCH)
#define WB_TOT  (WB_FC2 + 4*CCH*CCH)

// ---------------- scratch ----------------
__device__ __nv_bfloat16 g_ln1 [(size_t)MTOK*CCH];
__device__ __nv_bfloat16 g_ln2 [(size_t)MTOK*CCH];
__device__ __nv_bfloat16 g_qkv [(size_t)MTOK*3*CCH];
__device__ __nv_bfloat16 g_attn[(size_t)MTOK*CCH];
__device__ __nv_bfloat16 g_h1  [(size_t)MTOK*4*CCH];
__device__ __nv_bfloat16 g_wb  [WB_TOT];
__device__ float g_xres[(size_t)MTOK*CCH];
__device__ float g_btab[4*NHEAD*LW*LW];

__device__ __forceinline__ float gelu_exact(float x) {
    return 0.5f * x * (1.0f + erff(x * 0.70710678118654752f));
}
__device__ __forceinline__ uint32_t pack_bf16x2(float lo, float hi) {
    uint32_t o;
    asm("cvt.rn.bf16x2.f32 %0, %1, %2;" : "=r"(o) : "f"(hi), "f"(lo));
    return o;
}
__device__ __forceinline__ void mma_bf16(float c[4], const uint32_t a[4], const uint32_t b[2]) {
    asm volatile(
        "mma.sync.aligned.m16n8k16.row.col.f32.bf16.bf16.f32 "
        "{%0,%1,%2,%3}, {%4,%5,%6,%7}, {%8,%9}, {%0,%1,%2,%3};"
        : "+f"(c[0]), "+f"(c[1]), "+f"(c[2]), "+f"(c[3])
        : "r"(a[0]), "r"(a[1]), "r"(a[2]), "r"(a[3]), "r"(b[0]), "r"(b[1]));
}
#define LDSM4(r0, r1, r2, r3, addr)                                            \
    asm volatile("ldmatrix.sync.aligned.m8n8.x4.shared.b16 {%0,%1,%2,%3}, [%4];" \
                 : "=r"(r0), "=r"(r1), "=r"(r2), "=r"(r3) : "r"(addr))
__device__ __forceinline__ void cp_async16(uint32_t smem_addr, const void* gptr) {
    asm volatile("cp.async.cg.shared.global [%0], [%1], 16;" :: "r"(smem_addr), "l"(gptr));
}
__device__ __forceinline__ void cp_commit() { asm volatile("cp.async.commit_group;"); }
template<int N_> __device__ __forceinline__ void cp_wait() {
    asm volatile("cp.async.wait_group %0;" :: "n"(N_));
}

__device__ __forceinline__ int winrow_to_token(int wr) {
    const int w  = wr / LW, local = wr % LW;
    const int b  = w >> 6, wl = w & 63;
    const int hp = (wl >> 3)*WSZ + local/WSZ;
    const int wp = (wl & 7)*WSZ + local%WSZ;
    int h = hp + SHIFT_; if (h >= IMGH) h -= IMGH;
    int ww = wp + SHIFT_; if (ww >= IMGW) ww -= IMGW;
    return b*LLEN + h*IMGW + ww;
}
__device__ __forceinline__ int regid(int p) { return (p < 49) ? 0 : ((p < 53) ? 1 : 2); }

// ---------------- bias+mask table (once per launch) ----------------
__global__ void __launch_bounds__(256)
btab_kernel(const float* __restrict__ rel_bias)
{
    const int idx = blockIdx.x*256 + threadIdx.x;
    if (idx >= 4*NHEAD*LW*LW) return;
    const int j = idx % LW;
    const int i = (idx / LW) % LW;
    const int h = (idx / (LW*LW)) % NHEAD;
    const int p = idx / (NHEAD*LW*LW);
    const int wh = (p >> 1) ? 7 : 0;
    const int ww = (p & 1) ? 7 : 0;
    const int ih = i / WSZ, iw = i % WSZ;
    const int jh = j / WSZ, jw = j % WSZ;
    const int idi = regid(wh*WSZ + ih)*3 + regid(ww*WSZ + iw);
    const int idj = regid(wh*WSZ + jh)*3 + regid(ww*WSZ + jw);
    float v;
    if (idi != idj) v = -10000.0f;
    else            v = rel_bias[((ih - jh + 6)*13 + (iw - jw + 6))*NHEAD + h];
    g_btab[idx] = v;
}

// ---------------- weight fp32 -> bf16 conversion ----------------
__global__ void __launch_bounds__(256)
wconv_kernel(const float* __restrict__ w0, const float* __restrict__ w1,
             const float* __restrict__ w2, const float* __restrict__ w3)
{
    const int i = blockIdx.x*256 + threadIdx.x;
    const int n0 = 3*CCH*CCH/4, n1 = CCH*CCH/4, n2 = CCH*CCH;
    const float* src; int local; size_t off;
    if (i < n0)                { src = w0; local = i;            off = WB_QKV; }
    else if (i < n0+n1)        { src = w1; local = i - n0;       off = WB_PROJ; }
    else if (i < n0+n1+n2)     { src = w2; local = i - n0 - n1;  off = WB_FC1; }
    else if (i < n0+n1+2*n2)   { src = w3; local = i - n0-n1-n2; off = WB_FC2; }
    else return;
    const float4 v = reinterpret_cast<const float4*>(src)[local];
    uint2 o;
    o.x = pack_bf16x2(v.x, v.y);
    o.y = pack_bf16x2(v.z, v.w);
    *reinterpret_cast<uint2*>(&g_wb[off + (size_t)local*4]) = o;
}

// ---------------- LayerNorm: stats + normalize + bf16 store ----------------
__global__ void __launch_bounds__(256)
ln_norm_kernel(const float* __restrict__ in,
               const float* __restrict__ gamma, const float* __restrict__ beta,
               __nv_bfloat16* __restrict__ out)
{
    const int tok  = blockIdx.x*8 + (threadIdx.x >> 5);
    const int lane = threadIdx.x & 31;
    const float* p = in + (size_t)tok*CCH;

    float2 v[3];
    float s = 0.f, s2 = 0.f;
    #pragma unroll
    for (int i = 0; i < 3; ++i) {
        v[i] = *reinterpret_cast<const float2*>(&p[2*lane + 64*i]);
        s  += v[i].x + v[i].y;
        s2 += v[i].x*v[i].x + v[i].y*v[i].y;
    }
    #pragma unroll
    for (int off = 16; off > 0; off >>= 1) {
        s  += __shfl_xor_sync(0xffffffff, s,  off);
        s2 += __shfl_xor_sync(0xffffffff, s2, off);
    }
    const float mean = s * (1.0f/CCH);
    const float rstd = rsqrtf(s2 * (1.0f/CCH) - mean*mean + 1e-5f);

    #pragma unroll
    for (int i = 0; i < 3; ++i) {
        const float2 g = *reinterpret_cast<const float2*>(&gamma[2*lane + 64*i]);
        const float2 b = *reinterpret_cast<const float2*>(&beta [2*lane + 64*i]);
        const float y0 = (v[i].x - mean)*rstd*g.x + b.x;
        const float y1 = (v[i].y - mean)*rstd*g.y + b.y;
        *reinterpret_cast<uint32_t*>(&out[(size_t)tok*CCH + 2*lane + 64*i]) = pack_bf16x2(y0, y1);
    }
}

// ---------------- BF16 TC GEMM: BM=128, BN=96, BK=32, cp.async + ldmatrix ----------------
#define RS 20
#define ABUF (128*RS)
#define BBUF (96*RS)
#define SMEM_DYN (3*(ABUF+BBUF)*4)          // 53760 bytes
template<int ACT, bool HAS_BIAS, bool HAS_RES, bool GATHER, bool SCATTER, bool O_BF>
__global__ void __launch_bounds__(256)
gemm_tc(const __nv_bfloat16* __restrict__ A, const __nv_bfloat16* __restrict__ B,
        const float* __restrict__ bias, const float* __restrict__ res,
        void* __restrict__ outv, int M, int N, int K)
{
    float* outf = (float*)outv;
    __nv_bfloat16* outb = (__nv_bfloat16*)outv;

    extern __shared__ uint32_t smem_dyn[];
    uint32_t* sA = smem_dyn;                 // 3 stages of ABUF
    uint32_t* sB = smem_dyn + 3*ABUF;        // 3 stages of BBUF

    const int tid  = threadIdx.x;
    const int lane = tid & 31;
    const int warp = tid >> 5;
    const int warpM = warp & 3;              // 32-row slab
    const int warpN = warp >> 2;             // 48-col slab (0..1)
    const int m0 = blockIdx.y * 128;
    const int n0 = blockIdx.x * 96;

    float acc[2][6][4];
    #pragma unroll
    for (int i = 0; i < 2; ++i)
        #pragma unroll
        for (int j = 0; j < 6; ++j)
            #pragma unroll
            for (int q = 0; q < 4; ++q) acc[i][j][q] = 0.f;

    const int cRow  = tid >> 2;              // 0..63
    const int chunk = tid & 3;
    const int aSrc0 = GATHER ? winrow_to_token(m0 + cRow)      : m0 + cRow;
    const int aSrc1 = GATHER ? winrow_to_token(m0 + cRow + 64) : m0 + cRow + 64;

    const uint32_t saB  = (uint32_t)__cvta_generic_to_shared(&sA[cRow*RS + chunk*4]);
    const uint32_t sbB  = (uint32_t)__cvta_generic_to_shared(&sB[cRow*RS + chunk*4]);
    const uint32_t sbB2 = (uint32_t)__cvta_generic_to_shared(&sB[(64 + cRow)*RS + chunk*4]);
    const __nv_bfloat16* pa0 = &A[(size_t)aSrc0*K + chunk*8];
    const __nv_bfloat16* pa1 = &A[(size_t)aSrc1*K + chunk*8];
    const __nv_bfloat16* pb0 = &B[(size_t)(n0 + cRow)*K + chunk*8];
    const __nv_bfloat16* pb1 = &B[(size_t)(n0 + 64 + cRow)*K + chunk*8];   // used by tid<128

    #define ISSUE(s, k0)                                                   \
    {                                                                      \
        cp_async16(saB + (s)*(ABUF*4),            pa0 + (k0));             \
        cp_async16(saB + (s)*(ABUF*4) + 64*RS*4,  pa1 + (k0));             \
        cp_async16(sbB + (s)*(BBUF*4),            pb0 + (k0));             \
        if (tid < 128) cp_async16(sbB2 + (s)*(BBUF*4), pb1 + (k0));        \
        cp_commit();                                                       \
    }

    ISSUE(0, 0)
    ISSUE(1, 32)

    // ldmatrix per-lane base addresses
    const uint32_t aLdsm = (uint32_t)__cvta_generic_to_shared(
        &sA[(warpM*32 + (lane & 7) + ((lane >> 3) & 1)*8)*RS + ((lane >> 4) & 1)*4]);
    const uint32_t bLdsm = (uint32_t)__cvta_generic_to_shared(
        &sB[(warpN*48 + (lane & 7) + ((lane >> 4) & 1)*8)*RS + ((lane >> 3) & 1)*4]);

    const int ntiles = K >> 5;
    int st = 0;
    for (int t = 0; t < ntiles; ++t) {
        if (t < ntiles - 1) cp_wait<1>(); else cp_wait<0>();
        __syncthreads();
        if (t + 2 < ntiles) {
            const int s2 = (st + 2 >= 3) ? st - 1 : st + 2;
            ISSUE(s2, (t+2)*32)
        }

        const uint32_t aOff = aLdsm + st*(ABUF*4);
        const uint32_t bOff = bLdsm + st*(BBUF*4);
        #pragma unroll
        for (int ks = 0; ks < 2; ++ks) {
            uint32_t af[2][4], bf[6][2];
            LDSM4(af[0][0], af[0][1], af[0][2], af[0][3], aOff + ks*32);
            LDSM4(af[1][0], af[1][1], af[1][2], af[1][3], aOff + 16*RS*4 + ks*32);
            LDSM4(bf[0][0], bf[0][1], bf[1][0], bf[1][1], bOff + ks*32);
            LDSM4(bf[2][0], bf[2][1], bf[3][0], bf[3][1], bOff + 16*RS*4 + ks*32);
            LDSM4(bf[4][0], bf[4][1], bf[5][0], bf[5][1], bOff + 32*RS*4 + ks*32);
            #pragma unroll
            for (int mt = 0; mt < 2; ++mt)
                #pragma unroll
                for (int nt = 0; nt < 6; ++nt)
                    mma_bf16(acc[mt][nt], af[mt], bf[nt]);
        }
        st = (st == 2) ? 0 : st + 1;
    }
    #undef ISSUE

    const int laneR = lane >> 2;
    const int laneK = lane & 3;
    #pragma unroll
    for (int mt = 0; mt < 2; ++mt) {
        #pragma unroll
        for (int nt = 0; nt < 6; ++nt) {
            const int col = n0 + warpN*48 + nt*8 + (laneK << 1);
            const float b0 = HAS_BIAS ? bias[col]   : 0.f;
            const float b1 = HAS_BIAS ? bias[col+1] : 0.f;
            #pragma unroll
            for (int half = 0; half < 2; ++half) {
                const int wr = m0 + warpM*32 + mt*16 + laneR + half*8;
                const int row = SCATTER ? winrow_to_token(wr) : wr;
                float v0 = acc[mt][nt][half*2+0] + b0;
                float v1 = acc[mt][nt][half*2+1] + b1;
                if (ACT == 1) { v0 = gelu_exact(v0); v1 = gelu_exact(v1); }
                if (HAS_RES || SCATTER) {
                    const float2 r2 = *reinterpret_cast<const float2*>(&res[(size_t)row*N + col]);
                    v0 += r2.x; v1 += r2.y;
                }
                if (O_BF) {
                    *reinterpret_cast<uint32_t*>(&outb[(size_t)row*N + col]) = pack_bf16x2(v0, v1);
                } else {
                    *reinterpret_cast<float2*>(&outf[(size_t)row*N + col]) = make_float2(v0, v1);
                }
            }
        }
    }
}

// ---------------- fused attention, register-tiled, table-driven bias ----------------
__device__ __forceinline__ void bf8_to_smem_s(uint4 v, float* dst, float scale) {
    const __nv_bfloat162* b2 = reinterpret_cast<const __nv_bfloat162*>(&v);
    #pragma unroll
    for (int m = 0; m < 4; ++m) {
        const float2 f = __bfloat1622float2(b2[m]);
        dst[2*m]   = f.x * scale;
        dst[2*m+1] = f.y * scale;
    }
}

#define SSTR 52
__global__ void __launch_bounds__(128)
attn_kernel()
{
    const int h = blockIdx.x;
    const int w = blockIdx.y;
    const int tid = threadIdx.x;

    __shared__ float sQ[56*33];
    __shared__ float sK[64*33];
    __shared__ float sV[LW*32];
    __shared__ float sS[LW*SSTR];

    for (int t = tid; t < LW*HDIM/8; t += 128) {
        const int i = t >> 2, blk = (t & 3) << 3;
        const size_t base = (size_t)(w*LW + i) * (3*CCH) + h*HDIM + blk;
        bf8_to_smem_s(*reinterpret_cast<const uint4*>(&g_qkv[base]),         &sQ[i*33 + blk], QKSCALE);
        bf8_to_smem_s(*reinterpret_cast<const uint4*>(&g_qkv[base + CCH]),   &sK[i*33 + blk], 1.0f);
        bf8_to_smem_s(*reinterpret_cast<const uint4*>(&g_qkv[base + 2*CCH]), &sV[i*32 + blk], 1.0f);
    }
    __syncthreads();

    {
        const int ti = tid >> 4, tj = tid & 15;
        const int r0 = ti*7, c0 = tj*4;
        float acc[7][4];
        #pragma unroll
        for (int r = 0; r < 7; ++r)
            #pragma unroll
            for (int c = 0; c < 4; ++c) acc[r][c] = 0.f;
        #pragma unroll
        for (int d = 0; d < HDIM; ++d) {
            float kv[4];
            #pragma unroll
            for (int c = 0; c < 4; ++c) kv[c] = sK[(c0 + c)*33 + d];
            #pragma unroll
            for (int r = 0; r < 7; ++r) {
                const float qv = sQ[(r0 + r)*33 + d];
                #pragma unroll
                for (int c = 0; c < 4; ++c) acc[r][c] += qv * kv[c];
            }
        }
        const int wl  = w & (NWIN-1);
        const int pat = (((wl >> 3) == 7) ? 2 : 0) + (((wl & 7) == 7) ? 1 : 0);
        const float* bt = g_btab + (size_t)(pat*NHEAD + h)*LW*LW;
        #pragma unroll
        for (int r = 0; r < 7; ++r) {
            const int row = r0 + r;
            if (row < LW) {
                #pragma unroll
                for (int c = 0; c < 4; ++c) {
                    const int col = c0 + c;
                    if (col < LW)
                        sS[row*SSTR + col] = acc[r][c] + bt[row*LW + col];
                }
            }
        }
    }
    __syncthreads();

    if (tid < LW) {
        float* row = &sS[tid*SSTR];
        float mx = -1e30f;
        #pragma unroll
        for (int j = 0; j < LW; ++j) mx = fmaxf(mx, row[j]);
        float sum = 0.f;
        #pragma unroll
        for (int j = 0; j < LW; ++j) {
            const float e = __expf(row[j] - mx);
            row[j] = e;
            sum += e;
        }
        const float inv = 1.0f / sum;
        #pragma unroll
        for (int j = 0; j < LW; ++j) row[j] *= inv;
    }
    __syncthreads();

    {
        const int r0 = tid >> 2;
        const int r1 = r0 + 32;
        const int db = (tid & 3) << 3;
        float a0[8], a1[8];
        #pragma unroll
        for (int q = 0; q < 8; ++q) { a0[q] = 0.f; a1[q] = 0.f; }
        const bool has1 = (r1 < LW);
        for (int j = 0; j < LW; ++j) {
            const float p0 = sS[r0*SSTR + j];
            const float p1 = has1 ? sS[r1*SSTR + j] : 0.f;
            #pragma unroll
            for (int q = 0; q < 8; ++q) {
                const float vv = sV[j*32 + db + q];
                a0[q] += p0 * vv;
                a1[q] += p1 * vv;
            }
        }
        uint4 o;
        o.x = pack_bf16x2(a0[0], a0[1]);
        o.y = pack_bf16x2(a0[2], a0[3]);
        o.z = pack_bf16x2(a0[4], a0[5]);
        o.w = pack_bf16x2(a0[6], a0[7]);
        *reinterpret_cast<uint4*>(&g_attn[(size_t)(w*LW + r0)*CCH + h*HDIM + db]) = o;
        if (has1) {
            uint4 o1;
            o1.x = pack_bf16x2(a1[0], a1[1]);
            o1.y = pack_bf16x2(a1[2], a1[3]);
            o1.z = pack_bf16x2(a1[4], a1[5]);
            o1.w = pack_bf16x2(a1[6], a1[7]);
            *reinterpret_cast<uint4*>(&g_attn[(size_t)(w*LW + r1)*CCH + h*HDIM + db]) = o1;
        }
    }
}

// ---------------- launch ----------------
extern "C" void kernel_launch(void* const* d_in, const int* in_sizes, int n_in,
                              void* d_out, int out_size)
{
    const void* arr[20];
    int na = 0;
    for (int i = 0; i < n_in && na < 20; ++i)
        if (in_sizes[i] != 1) arr[na++] = d_in[i];
    const float* x     = (const float*)arr[0];
    const float* n1w   = (const float*)arr[3];
    const float* n1b   = (const float*)arr[4];
    const float* qkvw  = (const float*)arr[5];
    const float* relb  = (const float*)arr[6];
    const float* projw = (const float*)arr[7];
    const float* projb = (const float*)arr[8];
    const float* n2w   = (const float*)arr[9];
    const float* n2b   = (const float*)arr[10];
    const float* fc1w  = (const float*)arr[11];
    const float* fc1b  = (const float*)arr[12];
    const float* fc2w  = (const float*)arr[13];
    const float* fc2b  = (const float*)arr[14];
    float* out = (float*)d_out;

    __nv_bfloat16 *p_ln1, *p_ln2, *p_qkv, *p_attn, *p_h1, *p_wb;
    cudaGetSymbolAddress((void**)&p_ln1,  g_ln1);
    cudaGetSymbolAddress((void**)&p_ln2,  g_ln2);
    cudaGetSymbolAddress((void**)&p_qkv,  g_qkv);
    cudaGetSymbolAddress((void**)&p_attn, g_attn);
    cudaGetSymbolAddress((void**)&p_h1,   g_h1);
    cudaGetSymbolAddress((void**)&p_wb,   g_wb);
    float* p_xres; cudaGetSymbolAddress((void**)&p_xres, g_xres);

    // allow >48KB dynamic smem for each GEMM instantiation (host attr; capture-safe)
    static bool attr_done = false;
    if (!attr_done) {
        cudaFuncSetAttribute(gemm_tc<0, false, false, true,  false, true >,
                             cudaFuncAttributeMaxDynamicSharedMemorySize, SMEM_DYN);
        cudaFuncSetAttribute(gemm_tc<0, true,  false, false, true,  false>,
                             cudaFuncAttributeMaxDynamicSharedMemorySize, SMEM_DYN);
        cudaFuncSetAttribute(gemm_tc<1, true,  false, false, false, true >,
                             cudaFuncAttributeMaxDynamicSharedMemorySize, SMEM_DYN);
        cudaFuncSetAttribute(gemm_tc<1, true,  true,  false, false, false>,
                             cudaFuncAttributeMaxDynamicSharedMemorySize, SMEM_DYN);
        attr_done = true;
    }

    wconv_kernel<<<(WB_TOT/4 + 255)/256, 256>>>(qkvw, projw, fc1w, fc2w);
    btab_kernel<<<(4*NHEAD*LW*LW + 255)/256, 256>>>(relb);

    ln_norm_kernel<<<MTOK/8, 256>>>(x, n1w, n1b, p_ln1);

    // QKV: N=576 -> 6 n-blocks
    gemm_tc<0, false, false, true, false, true><<<dim3(576/96, MTOK/128), 256, SMEM_DYN>>>(
        p_ln1, p_wb + WB_QKV, nullptr, nullptr, p_qkv, MTOK, 3*CCH, CCH);

    attn_kernel<<<dim3(NHEAD, NWTOT), 128>>>();

    // proj: N=192 -> 2 n-blocks, scatter + residual
    gemm_tc<0, true, false, false, true, false><<<dim3(192/96, MTOK/128), 256, SMEM_DYN>>>(
        p_attn, p_wb + WB_PROJ, projb, x, p_xres, MTOK, CCH, CCH);

    ln_norm_kernel<<<MTOK/8, 256>>>(p_xres, n2w, n2b, p_ln2);

    // fc1: N=768 -> 8 n-blocks
    gemm_tc<1, true, false, false, false, true><<<dim3(768/96, MTOK/128), 256, SMEM_DYN>>>(
        p_ln2, p_wb + WB_FC1, fc1b, nullptr, p_h1, MTOK, 4*CCH, CCH);

    // fc2: N=192 -> 2 n-blocks, K=768
    gemm_tc<1, true, true, false, false, false><<<dim3(192/96, MTOK/128), 256, SMEM_DYN>>>(
        p_h1, p_wb + WB_FC2, fc2b, p_xres, out, MTOK, CCH, 4*CCH);

    (void)out_size;
}

// round 11
// speedup vs baseline: 1.6285x; 1.6285x over previous
#include <cuda_runtime.h>
#include <cuda_bf16.h>
#include <math.h>
#include <stdint.h>

// ---------------- static problem shape ----------------
#define BATCH 32
#define IMGH  56
#define IMGW  56
#define CCH   192
#define LLEN  (IMGH*IMGW)        // 3136
#define NHEAD 6
#define HDIM  32
#define WSZ   7
#define SHIFT_ 3
#define LW    49
#define NWIN  64
#define NWTOT (BATCH*NWIN)       // 2048
#define MTOK  (BATCH*LLEN)       // 100352
#define QKSCALE 13.856406460551018f

// bf16 weight buffer offsets (elements)
#define WB_QKV  0
#define WB_PROJ (WB_QKV + 3*CCH*CCH)
#define WB_FC1  (WB_PROJ + CCH*CCH)
#define WB_FC2  (WB_FC1 + 4*CCH*CCH)
#define WB_TOT  (WB_FC2 + 4*CCH*CCH)

// ---------------- scratch ----------------
__device__ __nv_bfloat16 g_ln1 [(size_t)MTOK*CCH];
__device__ __nv_bfloat16 g_ln2 [(size_t)MTOK*CCH];
__device__ __nv_bfloat16 g_qkv [(size_t)MTOK*3*CCH];
__device__ __nv_bfloat16 g_attn[(size_t)MTOK*CCH];
__device__ __nv_bfloat16 g_h1  [(size_t)MTOK*4*CCH];
__device__ __nv_bfloat16 g_wb  [WB_TOT];
__device__ float g_xres[(size_t)MTOK*CCH];
__device__ float g_btab[4*NHEAD*LW*LW];

__device__ __forceinline__ float gelu_exact(float x) {
    return 0.5f * x * (1.0f + erff(x * 0.70710678118654752f));
}
__device__ __forceinline__ uint32_t pack_bf16x2(float lo, float hi) {
    uint32_t o;
    asm("cvt.rn.bf16x2.f32 %0, %1, %2;" : "=r"(o) : "f"(hi), "f"(lo));
    return o;
}
__device__ __forceinline__ void mma_bf16(float c[4], const uint32_t a[4], const uint32_t b[2]) {
    asm volatile(
        "mma.sync.aligned.m16n8k16.row.col.f32.bf16.bf16.f32 "
        "{%0,%1,%2,%3}, {%4,%5,%6,%7}, {%8,%9}, {%0,%1,%2,%3};"
        : "+f"(c[0]), "+f"(c[1]), "+f"(c[2]), "+f"(c[3])
        : "r"(a[0]), "r"(a[1]), "r"(a[2]), "r"(a[3]), "r"(b[0]), "r"(b[1]));
}
#define LDSM4(r0, r1, r2, r3, addr)                                            \
    asm volatile("ldmatrix.sync.aligned.m8n8.x4.shared.b16 {%0,%1,%2,%3}, [%4];" \
                 : "=r"(r0), "=r"(r1), "=r"(r2), "=r"(r3) : "r"(addr))
__device__ __forceinline__ void cp_async16(uint32_t smem_addr, const void* gptr) {
    asm volatile("cp.async.cg.shared.global [%0], [%1], 16;" :: "r"(smem_addr), "l"(gptr));
}
__device__ __forceinline__ void cp_commit() { asm volatile("cp.async.commit_group;"); }
template<int N_> __device__ __forceinline__ void cp_wait() {
    asm volatile("cp.async.wait_group %0;" :: "n"(N_));
}

__device__ __forceinline__ int winrow_to_token(int wr) {
    const int w  = wr / LW, local = wr % LW;
    const int b  = w >> 6, wl = w & 63;
    const int hp = (wl >> 3)*WSZ + local/WSZ;
    const int wp = (wl & 7)*WSZ + local%WSZ;
    int h = hp + SHIFT_; if (h >= IMGH) h -= IMGH;
    int ww = wp + SHIFT_; if (ww >= IMGW) ww -= IMGW;
    return b*LLEN + h*IMGW + ww;
}
__device__ __forceinline__ int regid(int p) { return (p < 49) ? 0 : ((p < 53) ? 1 : 2); }

// ---------------- bias+mask table (once per launch) ----------------
__global__ void __launch_bounds__(256)
btab_kernel(const float* __restrict__ rel_bias)
{
    const int idx = blockIdx.x*256 + threadIdx.x;
    if (idx >= 4*NHEAD*LW*LW) return;
    const int j = idx % LW;
    const int i = (idx / LW) % LW;
    const int h = (idx / (LW*LW)) % NHEAD;
    const int p = idx / (NHEAD*LW*LW);
    const int wh = (p >> 1) ? 7 : 0;
    const int ww = (p & 1) ? 7 : 0;
    const int ih = i / WSZ, iw = i % WSZ;
    const int jh = j / WSZ, jw = j % WSZ;
    const int idi = regid(wh*WSZ + ih)*3 + regid(ww*WSZ + iw);
    const int idj = regid(wh*WSZ + jh)*3 + regid(ww*WSZ + jw);
    float v;
    if (idi != idj) v = -10000.0f;
    else            v = rel_bias[((ih - jh + 6)*13 + (iw - jw + 6))*NHEAD + h];
    g_btab[idx] = v;
}

// ---------------- weight fp32 -> bf16 conversion ----------------
__global__ void __launch_bounds__(256)
wconv_kernel(const float* __restrict__ w0, const float* __restrict__ w1,
             const float* __restrict__ w2, const float* __restrict__ w3)
{
    const int i = blockIdx.x*256 + threadIdx.x;
    const int n0 = 3*CCH*CCH/4, n1 = CCH*CCH/4, n2 = CCH*CCH;
    const float* src; int local; size_t off;
    if (i < n0)                { src = w0; local = i;            off = WB_QKV; }
    else if (i < n0+n1)        { src = w1; local = i - n0;       off = WB_PROJ; }
    else if (i < n0+n1+n2)     { src = w2; local = i - n0 - n1;  off = WB_FC1; }
    else if (i < n0+n1+2*n2)   { src = w3; local = i - n0-n1-n2; off = WB_FC2; }
    else return;
    const float4 v = reinterpret_cast<const float4*>(src)[local];
    uint2 o;
    o.x = pack_bf16x2(v.x, v.y);
    o.y = pack_bf16x2(v.z, v.w);
    *reinterpret_cast<uint2*>(&g_wb[off + (size_t)local*4]) = o;
}

// ---------------- LayerNorm: stats + normalize + bf16 store ----------------
__global__ void __launch_bounds__(256)
ln_norm_kernel(const float* __restrict__ in,
               const float* __restrict__ gamma, const float* __restrict__ beta,
               __nv_bfloat16* __restrict__ out)
{
    const int tok  = blockIdx.x*8 + (threadIdx.x >> 5);
    const int lane = threadIdx.x & 31;
    const float* p = in + (size_t)tok*CCH;

    float2 v[3];
    float s = 0.f, s2 = 0.f;
    #pragma unroll
    for (int i = 0; i < 3; ++i) {
        v[i] = *reinterpret_cast<const float2*>(&p[2*lane + 64*i]);
        s  += v[i].x + v[i].y;
        s2 += v[i].x*v[i].x + v[i].y*v[i].y;
    }
    #pragma unroll
    for (int off = 16; off > 0; off >>= 1) {
        s  += __shfl_xor_sync(0xffffffff, s,  off);
        s2 += __shfl_xor_sync(0xffffffff, s2, off);
    }
    const float mean = s * (1.0f/CCH);
    const float rstd = rsqrtf(s2 * (1.0f/CCH) - mean*mean + 1e-5f);

    #pragma unroll
    for (int i = 0; i < 3; ++i) {
        const float2 g = *reinterpret_cast<const float2*>(&gamma[2*lane + 64*i]);
        const float2 b = *reinterpret_cast<const float2*>(&beta [2*lane + 64*i]);
        const float y0 = (v[i].x - mean)*rstd*g.x + b.x;
        const float y1 = (v[i].y - mean)*rstd*g.y + b.y;
        *reinterpret_cast<uint32_t*>(&out[(size_t)tok*CCH + 2*lane + 64*i]) = pack_bf16x2(y0, y1);
    }
}

// ---------------- BF16 TC GEMM: BM=128, BN=64, BK=32, cp.async + ldmatrix ----------------
// __launch_bounds__(256, 4): force <=64 regs so 4 CTAs/SM co-reside (46KB smem x4 fits).
#define RS 20
#define ABUF (128*RS)
#define BBUF (64*RS)
template<int ACT, bool HAS_BIAS, bool HAS_RES, bool GATHER, bool SCATTER, bool O_BF>
__global__ void __launch_bounds__(256, 4)
gemm_tc(const __nv_bfloat16* __restrict__ A, const __nv_bfloat16* __restrict__ B,
        const float* __restrict__ bias, const float* __restrict__ res,
        void* __restrict__ outv, int M, int N, int K)
{
    float* outf = (float*)outv;
    __nv_bfloat16* outb = (__nv_bfloat16*)outv;

    const int tid  = threadIdx.x;
    const int lane = tid & 31;
    const int warp = tid >> 5;
    const int warpM = warp & 3;
    const int warpN = warp >> 2;
    const int m0 = blockIdx.y * 128;
    const int n0 = blockIdx.x * 64;

    __shared__ uint32_t sA[3*ABUF];
    __shared__ uint32_t sB[3*BBUF];

    float acc[2][4][4];
    #pragma unroll
    for (int i = 0; i < 2; ++i)
        #pragma unroll
        for (int j = 0; j < 4; ++j)
            #pragma unroll
            for (int q = 0; q < 4; ++q) acc[i][j][q] = 0.f;

    const int cRow  = tid >> 2;
    const int chunk = tid & 3;
    const int aSrc0 = GATHER ? winrow_to_token(m0 + cRow)      : m0 + cRow;
    const int aSrc1 = GATHER ? winrow_to_token(m0 + cRow + 64) : m0 + cRow + 64;

    const uint32_t saB = (uint32_t)__cvta_generic_to_shared(&sA[cRow*RS + chunk*4]);
    const uint32_t sbB = (uint32_t)__cvta_generic_to_shared(&sB[cRow*RS + chunk*4]);
    const __nv_bfloat16* pa0 = &A[(size_t)aSrc0*K + chunk*8];
    const __nv_bfloat16* pa1 = &A[(size_t)aSrc1*K + chunk*8];
    const __nv_bfloat16* pb  = &B[(size_t)(n0 + cRow)*K + chunk*8];

    #define ISSUE(s, k0)                                            \
    {                                                               \
        cp_async16(saB + (s)*(ABUF*4),              pa0 + (k0));    \
        cp_async16(saB + (s)*(ABUF*4) + 64*RS*4,    pa1 + (k0));    \
        cp_async16(sbB + (s)*(BBUF*4),              pb  + (k0));    \
        cp_commit();                                                \
    }

    ISSUE(0, 0)
    ISSUE(1, 32)

    const uint32_t aLdsm = (uint32_t)__cvta_generic_to_shared(
        &sA[(warpM*32 + (lane & 7) + ((lane >> 3) & 1)*8)*RS + ((lane >> 4) & 1)*4]);
    const uint32_t bLdsm = (uint32_t)__cvta_generic_to_shared(
        &sB[(warpN*32 + (lane & 7) + ((lane >> 4) & 1)*8)*RS + ((lane >> 3) & 1)*4]);

    const int ntiles = K >> 5;
    int st = 0;
    for (int t = 0; t < ntiles; ++t) {
        if (t < ntiles - 1) cp_wait<1>(); else cp_wait<0>();
        __syncthreads();
        if (t + 2 < ntiles) {
            const int s2 = (st + 2 >= 3) ? st - 1 : st + 2;
            ISSUE(s2, (t+2)*32)
        }

        const uint32_t aOff = aLdsm + st*(ABUF*4);
        const uint32_t bOff = bLdsm + st*(BBUF*4);
        #pragma unroll
        for (int ks = 0; ks < 2; ++ks) {
            uint32_t af[2][4], bf[4][2];
            LDSM4(af[0][0], af[0][1], af[0][2], af[0][3], aOff + ks*32);
            LDSM4(af[1][0], af[1][1], af[1][2], af[1][3], aOff + 16*RS*4 + ks*32);
            LDSM4(bf[0][0], bf[0][1], bf[1][0], bf[1][1], bOff + ks*32);
            LDSM4(bf[2][0], bf[2][1], bf[3][0], bf[3][1], bOff + 16*RS*4 + ks*32);
            #pragma unroll
            for (int mt = 0; mt < 2; ++mt)
                #pragma unroll
                for (int nt = 0; nt < 4; ++nt)
                    mma_bf16(acc[mt][nt], af[mt], bf[nt]);
        }
        st = (st == 2) ? 0 : st + 1;
    }
    #undef ISSUE

    const int laneR = lane >> 2;
    const int laneK = lane & 3;
    #pragma unroll
    for (int mt = 0; mt < 2; ++mt) {
        #pragma unroll
        for (int nt = 0; nt < 4; ++nt) {
            const int col = n0 + warpN*32 + nt*8 + (laneK << 1);
            const float b0 = HAS_BIAS ? bias[col]   : 0.f;
            const float b1 = HAS_BIAS ? bias[col+1] : 0.f;
            #pragma unroll
            for (int half = 0; half < 2; ++half) {
                const int wr = m0 + warpM*32 + mt*16 + laneR + half*8;
                const int row = SCATTER ? winrow_to_token(wr) : wr;
                float v0 = acc[mt][nt][half*2+0] + b0;
                float v1 = acc[mt][nt][half*2+1] + b1;
                if (ACT == 1) { v0 = gelu_exact(v0); v1 = gelu_exact(v1); }
                if (HAS_RES || SCATTER) {
                    const float2 r2 = *reinterpret_cast<const float2*>(&res[(size_t)row*N + col]);
                    v0 += r2.x; v1 += r2.y;
                }
                if (O_BF) {
                    *reinterpret_cast<uint32_t*>(&outb[(size_t)row*N + col]) = pack_bf16x2(v0, v1);
                } else {
                    *reinterpret_cast<float2*>(&outf[(size_t)row*N + col]) = make_float2(v0, v1);
                }
            }
        }
    }
}

// ---------------- fused attention, register-tiled, table-driven bias ----------------
__device__ __forceinline__ void bf8_to_smem_s(uint4 v, float* dst, float scale) {
    const __nv_bfloat162* b2 = reinterpret_cast<const __nv_bfloat162*>(&v);
    #pragma unroll
    for (int m = 0; m < 4; ++m) {
        const float2 f = __bfloat1622float2(b2[m]);
        dst[2*m]   = f.x * scale;
        dst[2*m+1] = f.y * scale;
    }
}

#define SSTR 52
__global__ void __launch_bounds__(128)
attn_kernel()
{
    const int h = blockIdx.x;
    const int w = blockIdx.y;
    const int tid = threadIdx.x;

    __shared__ float sQ[56*33];
    __shared__ float sK[64*33];
    __shared__ float sV[LW*32];
    __shared__ float sS[LW*SSTR];

    for (int t = tid; t < LW*HDIM/8; t += 128) {
        const int i = t >> 2, blk = (t & 3) << 3;
        const size_t base = (size_t)(w*LW + i) * (3*CCH) + h*HDIM + blk;
        bf8_to_smem_s(*reinterpret_cast<const uint4*>(&g_qkv[base]),         &sQ[i*33 + blk], QKSCALE);
        bf8_to_smem_s(*reinterpret_cast<const uint4*>(&g_qkv[base + CCH]),   &sK[i*33 + blk], 1.0f);
        bf8_to_smem_s(*reinterpret_cast<const uint4*>(&g_qkv[base + 2*CCH]), &sV[i*32 + blk], 1.0f);
    }
    __syncthreads();

    {
        const int ti = tid >> 4, tj = tid & 15;
        const int r0 = ti*7, c0 = tj*4;
        float acc[7][4];
        #pragma unroll
        for (int r = 0; r < 7; ++r)
            #pragma unroll
            for (int c = 0; c < 4; ++c) acc[r][c] = 0.f;
        #pragma unroll
        for (int d = 0; d < HDIM; ++d) {
            float kv[4];
            #pragma unroll
            for (int c = 0; c < 4; ++c) kv[c] = sK[(c0 + c)*33 + d];
            #pragma unroll
            for (int r = 0; r < 7; ++r) {
                const float qv = sQ[(r0 + r)*33 + d];
                #pragma unroll
                for (int c = 0; c < 4; ++c) acc[r][c] += qv * kv[c];
            }
        }
        const int wl  = w & (NWIN-1);
        const int pat = (((wl >> 3) == 7) ? 2 : 0) + (((wl & 7) == 7) ? 1 : 0);
        const float* bt = g_btab + (size_t)(pat*NHEAD + h)*LW*LW;
        #pragma unroll
        for (int r = 0; r < 7; ++r) {
            const int row = r0 + r;
            if (row < LW) {
                #pragma unroll
                for (int c = 0; c < 4; ++c) {
                    const int col = c0 + c;
                    if (col < LW)
                        sS[row*SSTR + col] = acc[r][c] + bt[row*LW + col];
                }
            }
        }
    }
    __syncthreads();

    if (tid < LW) {
        float* row = &sS[tid*SSTR];
        float mx = -1e30f;
        #pragma unroll
        for (int j = 0; j < LW; ++j) mx = fmaxf(mx, row[j]);
        float sum = 0.f;
        #pragma unroll
        for (int j = 0; j < LW; ++j) {
            const float e = __expf(row[j] - mx);
            row[j] = e;
            sum += e;
        }
        const float inv = 1.0f / sum;
        #pragma unroll
        for (int j = 0; j < LW; ++j) row[j] *= inv;
    }
    __syncthreads();

    {
        const int r0 = tid >> 2;
        const int r1 = r0 + 32;
        const int db = (tid & 3) << 3;
        float a0[8], a1[8];
        #pragma unroll
        for (int q = 0; q < 8; ++q) { a0[q] = 0.f; a1[q] = 0.f; }
        const bool has1 = (r1 < LW);
        for (int j = 0; j < LW; ++j) {
            const float p0 = sS[r0*SSTR + j];
            const float p1 = has1 ? sS[r1*SSTR + j] : 0.f;
            #pragma unroll
            for (int q = 0; q < 8; ++q) {
                const float vv = sV[j*32 + db + q];
                a0[q] += p0 * vv;
                a1[q] += p1 * vv;
            }
        }
        uint4 o;
        o.x = pack_bf16x2(a0[0], a0[1]);
        o.y = pack_bf16x2(a0[2], a0[3]);
        o.z = pack_bf16x2(a0[4], a0[5]);
        o.w = pack_bf16x2(a0[6], a0[7]);
        *reinterpret_cast<uint4*>(&g_attn[(size_t)(w*LW + r0)*CCH + h*HDIM + db]) = o;
        if (has1) {
            uint4 o1;
            o1.x = pack_bf16x2(a1[0], a1[1]);
            o1.y = pack_bf16x2(a1[2], a1[3]);
            o1.z = pack_bf16x2(a1[4], a1[5]);
            o1.w = pack_bf16x2(a1[6], a1[7]);
            *reinterpret_cast<uint4*>(&g_attn[(size_t)(w*LW + r1)*CCH + h*HDIM + db]) = o1;
        }
    }
}

// ---------------- launch ----------------
extern "C" void kernel_launch(void* const* d_in, const int* in_sizes, int n_in,
                              void* d_out, int out_size)
{
    const void* arr[20];
    int na = 0;
    for (int i = 0; i < n_in && na < 20; ++i)
        if (in_sizes[i] != 1) arr[na++] = d_in[i];
    const float* x     = (const float*)arr[0];
    const float* n1w   = (const float*)arr[3];
    const float* n1b   = (const float*)arr[4];
    const float* qkvw  = (const float*)arr[5];
    const float* relb  = (const float*)arr[6];
    const float* projw = (const float*)arr[7];
    const float* projb = (const float*)arr[8];
    const float* n2w   = (const float*)arr[9];
    const float* n2b   = (const float*)arr[10];
    const float* fc1w  = (const float*)arr[11];
    const float* fc1b  = (const float*)arr[12];
    const float* fc2w  = (const float*)arr[13];
    const float* fc2b  = (const float*)arr[14];
    float* out = (float*)d_out;

    __nv_bfloat16 *p_ln1, *p_ln2, *p_qkv, *p_attn, *p_h1, *p_wb;
    cudaGetSymbolAddress((void**)&p_ln1,  g_ln1);
    cudaGetSymbolAddress((void**)&p_ln2,  g_ln2);
    cudaGetSymbolAddress((void**)&p_qkv,  g_qkv);
    cudaGetSymbolAddress((void**)&p_attn, g_attn);
    cudaGetSymbolAddress((void**)&p_h1,   g_h1);
    cudaGetSymbolAddress((void**)&p_wb,   g_wb);
    float* p_xres; cudaGetSymbolAddress((void**)&p_xres, g_xres);

    wconv_kernel<<<(WB_TOT/4 + 255)/256, 256>>>(qkvw, projw, fc1w, fc2w);
    btab_kernel<<<(4*NHEAD*LW*LW + 255)/256, 256>>>(relb);

    ln_norm_kernel<<<MTOK/8, 256>>>(x, n1w, n1b, p_ln1);

    gemm_tc<0, false, false, true, false, true><<<dim3(576/64, MTOK/128), 256>>>(
        p_ln1, p_wb + WB_QKV, nullptr, nullptr, p_qkv, MTOK, 3*CCH, CCH);

    attn_kernel<<<dim3(NHEAD, NWTOT), 128>>>();

    gemm_tc<0, true, false, false, true, false><<<dim3(192/64, MTOK/128), 256>>>(
        p_attn, p_wb + WB_PROJ, projb, x, p_xres, MTOK, CCH, CCH);

    ln_norm_kernel<<<MTOK/8, 256>>>(p_xres, n2w, n2b, p_ln2);

    gemm_tc<1, true, false, false, false, true><<<dim3(768/64, MTOK/128), 256>>>(
        p_ln2, p_wb + WB_FC1, fc1b, nullptr, p_h1, MTOK, 4*CCH, CCH);

    gemm_tc<1, true, true, false, false, false><<<dim3(192/64, MTOK/128), 256>>>(
        p_h1, p_wb + WB_FC2, fc2b, p_xres, out, MTOK, CCH, 4*CCH);

    (void)out_size;
}

// round 12
// speedup vs baseline: 1.8817x; 1.1554x over previous
#include <cuda_runtime.h>
#include <cuda_bf16.h>
#include <math.h>
#include <stdint.h>

// ---------------- static problem shape ----------------
#define BATCH 32
#define IMGH  56
#define IMGW  56
#define CCH   192
#define LLEN  (IMGH*IMGW)        // 3136
#define NHEAD 6
#define HDIM  32
#define WSZ   7
#define SHIFT_ 3
#define LW    49
#define NWIN  64
#define NWTOT (BATCH*NWIN)       // 2048
#define MTOK  (BATCH*LLEN)       // 100352
#define QKSCALE 13.856406460551018f

// bf16 weight buffer offsets (elements)
#define WB_QKV  0
#define WB_PROJ (WB_QKV + 3*CCH*CCH)
#define WB_FC1  (WB_PROJ + CCH*CCH)
#define WB_FC2  (WB_FC1 + 4*CCH*CCH)
#define WB_TOT  (WB_FC2 + 4*CCH*CCH)

// ---------------- scratch ----------------
__device__ __nv_bfloat16 g_ln1 [(size_t)MTOK*CCH];
__device__ __nv_bfloat16 g_ln2 [(size_t)MTOK*CCH];
__device__ __nv_bfloat16 g_qkv [(size_t)MTOK*3*CCH];
__device__ __nv_bfloat16 g_attn[(size_t)MTOK*CCH];
__device__ __nv_bfloat16 g_h1  [(size_t)MTOK*4*CCH];
__device__ __nv_bfloat16 g_wb  [WB_TOT];
__device__ float g_xres[(size_t)MTOK*CCH];
__device__ float g_btab[4*NHEAD*LW*LW];

__device__ __forceinline__ float gelu_exact(float x) {
    return 0.5f * x * (1.0f + erff(x * 0.70710678118654752f));
}
__device__ __forceinline__ uint32_t pack_bf16x2(float lo, float hi) {
    uint32_t o;
    asm("cvt.rn.bf16x2.f32 %0, %1, %2;" : "=r"(o) : "f"(hi), "f"(lo));
    return o;
}
__device__ __forceinline__ void mma_bf16(float c[4], const uint32_t a[4], const uint32_t b[2]) {
    asm volatile(
        "mma.sync.aligned.m16n8k16.row.col.f32.bf16.bf16.f32 "
        "{%0,%1,%2,%3}, {%4,%5,%6,%7}, {%8,%9}, {%0,%1,%2,%3};"
        : "+f"(c[0]), "+f"(c[1]), "+f"(c[2]), "+f"(c[3])
        : "r"(a[0]), "r"(a[1]), "r"(a[2]), "r"(a[3]), "r"(b[0]), "r"(b[1]));
}
#define LDSM4(r0, r1, r2, r3, addr)                                            \
    asm volatile("ldmatrix.sync.aligned.m8n8.x4.shared.b16 {%0,%1,%2,%3}, [%4];" \
                 : "=r"(r0), "=r"(r1), "=r"(r2), "=r"(r3) : "r"(addr))
#define LDSM4T(r0, r1, r2, r3, addr)                                           \
    asm volatile("ldmatrix.sync.aligned.m8n8.x4.trans.shared.b16 {%0,%1,%2,%3}, [%4];" \
                 : "=r"(r0), "=r"(r1), "=r"(r2), "=r"(r3) : "r"(addr))
__device__ __forceinline__ void cp_async16(uint32_t smem_addr, const void* gptr) {
    asm volatile("cp.async.cg.shared.global [%0], [%1], 16;" :: "r"(smem_addr), "l"(gptr));
}
__device__ __forceinline__ void cp_commit() { asm volatile("cp.async.commit_group;"); }
template<int N_> __device__ __forceinline__ void cp_wait() {
    asm volatile("cp.async.wait_group %0;" :: "n"(N_));
}

__device__ __forceinline__ int winrow_to_token(int wr) {
    const int w  = wr / LW, local = wr % LW;
    const int b  = w >> 6, wl = w & 63;
    const int hp = (wl >> 3)*WSZ + local/WSZ;
    const int wp = (wl & 7)*WSZ + local%WSZ;
    int h = hp + SHIFT_; if (h >= IMGH) h -= IMGH;
    int ww = wp + SHIFT_; if (ww >= IMGW) ww -= IMGW;
    return b*LLEN + h*IMGW + ww;
}
__device__ __forceinline__ int regid(int p) { return (p < 49) ? 0 : ((p < 53) ? 1 : 2); }

// ---------------- bias+mask table (once per launch) ----------------
__global__ void __launch_bounds__(256)
btab_kernel(const float* __restrict__ rel_bias)
{
    const int idx = blockIdx.x*256 + threadIdx.x;
    if (idx >= 4*NHEAD*LW*LW) return;
    const int j = idx % LW;
    const int i = (idx / LW) % LW;
    const int h = (idx / (LW*LW)) % NHEAD;
    const int p = idx / (NHEAD*LW*LW);
    const int wh = (p >> 1) ? 7 : 0;
    const int ww = (p & 1) ? 7 : 0;
    const int ih = i / WSZ, iw = i % WSZ;
    const int jh = j / WSZ, jw = j % WSZ;
    const int idi = regid(wh*WSZ + ih)*3 + regid(ww*WSZ + iw);
    const int idj = regid(wh*WSZ + jh)*3 + regid(ww*WSZ + jw);
    float v;
    if (idi != idj) v = -10000.0f;
    else            v = rel_bias[((ih - jh + 6)*13 + (iw - jw + 6))*NHEAD + h];
    g_btab[idx] = v;
}

// ---------------- weight fp32 -> bf16 conversion ----------------
__global__ void __launch_bounds__(256)
wconv_kernel(const float* __restrict__ w0, const float* __restrict__ w1,
             const float* __restrict__ w2, const float* __restrict__ w3)
{
    const int i = blockIdx.x*256 + threadIdx.x;
    const int n0 = 3*CCH*CCH/4, n1 = CCH*CCH/4, n2 = CCH*CCH;
    const float* src; int local; size_t off;
    if (i < n0)                { src = w0; local = i;            off = WB_QKV; }
    else if (i < n0+n1)        { src = w1; local = i - n0;       off = WB_PROJ; }
    else if (i < n0+n1+n2)     { src = w2; local = i - n0 - n1;  off = WB_FC1; }
    else if (i < n0+n1+2*n2)   { src = w3; local = i - n0-n1-n2; off = WB_FC2; }
    else return;
    const float4 v = reinterpret_cast<const float4*>(src)[local];
    uint2 o;
    o.x = pack_bf16x2(v.x, v.y);
    o.y = pack_bf16x2(v.z, v.w);
    *reinterpret_cast<uint2*>(&g_wb[off + (size_t)local*4]) = o;
}

// ---------------- LayerNorm: stats + normalize + bf16 store ----------------
__global__ void __launch_bounds__(256)
ln_norm_kernel(const float* __restrict__ in,
               const float* __restrict__ gamma, const float* __restrict__ beta,
               __nv_bfloat16* __restrict__ out)
{
    const int tok  = blockIdx.x*8 + (threadIdx.x >> 5);
    const int lane = threadIdx.x & 31;
    const float* p = in + (size_t)tok*CCH;

    float2 v[3];
    float s = 0.f, s2 = 0.f;
    #pragma unroll
    for (int i = 0; i < 3; ++i) {
        v[i] = *reinterpret_cast<const float2*>(&p[2*lane + 64*i]);
        s  += v[i].x + v[i].y;
        s2 += v[i].x*v[i].x + v[i].y*v[i].y;
    }
    #pragma unroll
    for (int off = 16; off > 0; off >>= 1) {
        s  += __shfl_xor_sync(0xffffffff, s,  off);
        s2 += __shfl_xor_sync(0xffffffff, s2, off);
    }
    const float mean = s * (1.0f/CCH);
    const float rstd = rsqrtf(s2 * (1.0f/CCH) - mean*mean + 1e-5f);

    #pragma unroll
    for (int i = 0; i < 3; ++i) {
        const float2 g = *reinterpret_cast<const float2*>(&gamma[2*lane + 64*i]);
        const float2 b = *reinterpret_cast<const float2*>(&beta [2*lane + 64*i]);
        const float y0 = (v[i].x - mean)*rstd*g.x + b.x;
        const float y1 = (v[i].y - mean)*rstd*g.y + b.y;
        *reinterpret_cast<uint32_t*>(&out[(size_t)tok*CCH + 2*lane + 64*i]) = pack_bf16x2(y0, y1);
    }
}

// ---------------- BF16 TC GEMM: BM=128, BN=64, BK=32, cp.async + ldmatrix ----------------
#define RS 20
#define ABUF (128*RS)
#define BBUF (64*RS)
template<int ACT, bool HAS_BIAS, bool HAS_RES, bool GATHER, bool SCATTER, bool O_BF>
__global__ void __launch_bounds__(256, 4)
gemm_tc(const __nv_bfloat16* __restrict__ A, const __nv_bfloat16* __restrict__ B,
        const float* __restrict__ bias, const float* __restrict__ res,
        void* __restrict__ outv, int M, int N, int K)
{
    float* outf = (float*)outv;
    __nv_bfloat16* outb = (__nv_bfloat16*)outv;

    const int tid  = threadIdx.x;
    const int lane = tid & 31;
    const int warp = tid >> 5;
    const int warpM = warp & 3;
    const int warpN = warp >> 2;
    const int m0 = blockIdx.y * 128;
    const int n0 = blockIdx.x * 64;

    __shared__ uint32_t sA[3*ABUF];
    __shared__ uint32_t sB[3*BBUF];

    float acc[2][4][4];
    #pragma unroll
    for (int i = 0; i < 2; ++i)
        #pragma unroll
        for (int j = 0; j < 4; ++j)
            #pragma unroll
            for (int q = 0; q < 4; ++q) acc[i][j][q] = 0.f;

    const int cRow  = tid >> 2;
    const int chunk = tid & 3;
    const int aSrc0 = GATHER ? winrow_to_token(m0 + cRow)      : m0 + cRow;
    const int aSrc1 = GATHER ? winrow_to_token(m0 + cRow + 64) : m0 + cRow + 64;

    const uint32_t saB = (uint32_t)__cvta_generic_to_shared(&sA[cRow*RS + chunk*4]);
    const uint32_t sbB = (uint32_t)__cvta_generic_to_shared(&sB[cRow*RS + chunk*4]);
    const __nv_bfloat16* pa0 = &A[(size_t)aSrc0*K + chunk*8];
    const __nv_bfloat16* pa1 = &A[(size_t)aSrc1*K + chunk*8];
    const __nv_bfloat16* pb  = &B[(size_t)(n0 + cRow)*K + chunk*8];

    #define ISSUE(s, k0)                                            \
    {                                                               \
        cp_async16(saB + (s)*(ABUF*4),              pa0 + (k0));    \
        cp_async16(saB + (s)*(ABUF*4) + 64*RS*4,    pa1 + (k0));    \
        cp_async16(sbB + (s)*(BBUF*4),              pb  + (k0));    \
        cp_commit();                                                \
    }

    ISSUE(0, 0)
    ISSUE(1, 32)

    const uint32_t aLdsm = (uint32_t)__cvta_generic_to_shared(
        &sA[(warpM*32 + (lane & 7) + ((lane >> 3) & 1)*8)*RS + ((lane >> 4) & 1)*4]);
    const uint32_t bLdsm = (uint32_t)__cvta_generic_to_shared(
        &sB[(warpN*32 + (lane & 7) + ((lane >> 4) & 1)*8)*RS + ((lane >> 3) & 1)*4]);

    const int ntiles = K >> 5;
    int st = 0;
    for (int t = 0; t < ntiles; ++t) {
        if (t < ntiles - 1) cp_wait<1>(); else cp_wait<0>();
        __syncthreads();
        if (t + 2 < ntiles) {
            const int s2 = (st + 2 >= 3) ? st - 1 : st + 2;
            ISSUE(s2, (t+2)*32)
        }

        const uint32_t aOff = aLdsm + st*(ABUF*4);
        const uint32_t bOff = bLdsm + st*(BBUF*4);
        #pragma unroll
        for (int ks = 0; ks < 2; ++ks) {
            uint32_t af[2][4], bf[4][2];
            LDSM4(af[0][0], af[0][1], af[0][2], af[0][3], aOff + ks*32);
            LDSM4(af[1][0], af[1][1], af[1][2], af[1][3], aOff + 16*RS*4 + ks*32);
            LDSM4(bf[0][0], bf[0][1], bf[1][0], bf[1][1], bOff + ks*32);
            LDSM4(bf[2][0], bf[2][1], bf[3][0], bf[3][1], bOff + 16*RS*4 + ks*32);
            #pragma unroll
            for (int mt = 0; mt < 2; ++mt)
                #pragma unroll
                for (int nt = 0; nt < 4; ++nt)
                    mma_bf16(acc[mt][nt], af[mt], bf[nt]);
        }
        st = (st == 2) ? 0 : st + 1;
    }
    #undef ISSUE

    const int laneR = lane >> 2;
    const int laneK = lane & 3;
    #pragma unroll
    for (int mt = 0; mt < 2; ++mt) {
        #pragma unroll
        for (int nt = 0; nt < 4; ++nt) {
            const int col = n0 + warpN*32 + nt*8 + (laneK << 1);
            const float b0 = HAS_BIAS ? bias[col]   : 0.f;
            const float b1 = HAS_BIAS ? bias[col+1] : 0.f;
            #pragma unroll
            for (int half = 0; half < 2; ++half) {
                const int wr = m0 + warpM*32 + mt*16 + laneR + half*8;
                const int row = SCATTER ? winrow_to_token(wr) : wr;
                float v0 = acc[mt][nt][half*2+0] + b0;
                float v1 = acc[mt][nt][half*2+1] + b1;
                if (ACT == 1) { v0 = gelu_exact(v0); v1 = gelu_exact(v1); }
                if (HAS_RES || SCATTER) {
                    const float2 r2 = *reinterpret_cast<const float2*>(&res[(size_t)row*N + col]);
                    v0 += r2.x; v1 += r2.y;
                }
                if (O_BF) {
                    *reinterpret_cast<uint32_t*>(&outb[(size_t)row*N + col]) = pack_bf16x2(v0, v1);
                } else {
                    *reinterpret_cast<float2*>(&outf[(size_t)row*N + col]) = make_float2(v0, v1);
                }
            }
        }
    }
}

// ---------------- fused attention on tensor cores ----------------
// block = (head, window), 128 threads (4 warps). All operands bf16 in smem.
// QK^T: M=64(pad of 49) x N=64 x K=32; PV: M=64 x N=32 x K=64(pad of 49).
#define QSTR 40     // bf16 row stride for Q/K/V (80B: 16B-aligned, LDSM conflict-free)
#define PSTR 72     // bf16 row stride for P (144B)
#define SSTRF 68    // fp32 row stride for S

__global__ void __launch_bounds__(128)
attn_kernel()
{
    const int h = blockIdx.x;
    const int w = blockIdx.y;
    const int tid = threadIdx.x;
    const int lane = tid & 31;
    const int wi = tid >> 5;

    __shared__ __nv_bfloat16 sQ[64*QSTR];
    __shared__ __nv_bfloat16 sK[64*QSTR];
    __shared__ __nv_bfloat16 sV[64*QSTR];
    __shared__ float sS[LW*SSTRF];
    __shared__ __nv_bfloat16 sP[64*PSTR];

    // load Q,K,V raw bf16 (49 rows x 32, uint4 = 8 bf16)
    for (int t = tid; t < LW*4; t += 128) {
        const int i = t >> 2, blk = (t & 3) << 3;
        const size_t base = (size_t)(w*LW + i)*(3*CCH) + h*HDIM + blk;
        *reinterpret_cast<uint4*>(&sQ[i*QSTR + blk]) = *reinterpret_cast<const uint4*>(&g_qkv[base]);
        *reinterpret_cast<uint4*>(&sK[i*QSTR + blk]) = *reinterpret_cast<const uint4*>(&g_qkv[base + CCH]);
        *reinterpret_cast<uint4*>(&sV[i*QSTR + blk]) = *reinterpret_cast<const uint4*>(&g_qkv[base + 2*CCH]);
    }
    // zero V pad rows 49..63 (P pad cols are exact 0; avoid 0*NaN)
    for (int t = tid; t < 15*QSTR/2; t += 128)
        reinterpret_cast<uint32_t*>(&sV[49*QSTR])[t] = 0;
    __syncthreads();

    const int mB = wi*16;
    const int laneR = lane >> 2, laneK = lane & 3;
    const int r0 = mB + laneR, r1 = r0 + 8;

    // ---- QK^T ----
    float acc[8][4];
    #pragma unroll
    for (int i = 0; i < 8; ++i)
        #pragma unroll
        for (int q = 0; q < 4; ++q) acc[i][q] = 0.f;

    const uint32_t aAddr = (uint32_t)__cvta_generic_to_shared(
        &sQ[(mB + (lane & 7) + ((lane >> 3) & 1)*8)*QSTR + ((lane >> 4) & 1)*8]);
    const uint32_t kAddr = (uint32_t)__cvta_generic_to_shared(
        &sK[((lane & 7) + ((lane >> 4) & 1)*8)*QSTR + ((lane >> 3) & 1)*8]);

    #pragma unroll
    for (int ks = 0; ks < 2; ++ks) {
        uint32_t a[4];
        LDSM4(a[0], a[1], a[2], a[3], aAddr + ks*32);
        #pragma unroll
        for (int nb = 0; nb < 4; ++nb) {
            uint32_t b0[2], b1[2];
            LDSM4(b0[0], b0[1], b1[0], b1[1], kAddr + nb*(16*QSTR*2) + ks*32);
            mma_bf16(acc[nb*2+0], a, b0);
            mma_bf16(acc[nb*2+1], a, b1);
        }
    }

    // S = acc*scale + bias/mask table; pad cols -> -1e4
    {
        const int wl = w & (NWIN-1);
        const int pat = (((wl >> 3) == 7) ? 2 : 0) + (((wl & 7) == 7) ? 1 : 0);
        const float* bt = g_btab + (size_t)(pat*NHEAD + h)*LW*LW;
        #pragma unroll
        for (int nt = 0; nt < 8; ++nt) {
            const int c0 = nt*8 + 2*laneK;
            if (r0 < LW) {
                sS[r0*SSTRF + c0]   = (c0   < LW) ? acc[nt][0]*QKSCALE + bt[r0*LW + c0]   : -10000.f;
                sS[r0*SSTRF + c0+1] = (c0+1 < LW) ? acc[nt][1]*QKSCALE + bt[r0*LW + c0+1] : -10000.f;
            }
            if (r1 < LW) {
                sS[r1*SSTRF + c0]   = (c0   < LW) ? acc[nt][2]*QKSCALE + bt[r1*LW + c0]   : -10000.f;
                sS[r1*SSTRF + c0+1] = (c0+1 < LW) ? acc[nt][3]*QKSCALE + bt[r1*LW + c0+1] : -10000.f;
            }
        }
    }
    __syncthreads();

    // softmax over 64 cols (pad cols exp->0), write bf16 P
    if (tid < LW) {
        float* row = &sS[tid*SSTRF];
        float mx = -1e30f;
        #pragma unroll
        for (int j = 0; j < 64; ++j) mx = fmaxf(mx, row[j]);
        float sum = 0.f;
        #pragma unroll
        for (int j = 0; j < 64; ++j) {
            const float e = __expf(row[j] - mx);
            row[j] = e;
            sum += e;
        }
        const float inv = 1.0f / sum;
        uint32_t* prow = reinterpret_cast<uint32_t*>(&sP[tid*PSTR]);
        #pragma unroll
        for (int j = 0; j < 32; ++j)
            prow[j] = pack_bf16x2(row[2*j]*inv, row[2*j+1]*inv);
    }
    __syncthreads();

    // ---- PV: out = P @ V ----
    float acc2[4][4];
    #pragma unroll
    for (int i = 0; i < 4; ++i)
        #pragma unroll
        for (int q = 0; q < 4; ++q) acc2[i][q] = 0.f;

    const uint32_t pAddr = (uint32_t)__cvta_generic_to_shared(
        &sP[(mB + (lane & 7) + ((lane >> 3) & 1)*8)*PSTR + ((lane >> 4) & 1)*8]);
    const uint32_t vAddr = (uint32_t)__cvta_generic_to_shared(
        &sV[((lane & 7) + ((lane >> 3) & 1)*8)*QSTR + ((lane >> 4) & 1)*8]);

    #pragma unroll
    for (int ks = 0; ks < 4; ++ks) {
        uint32_t a[4];
        LDSM4(a[0], a[1], a[2], a[3], pAddr + ks*32);
        uint32_t b[4][2];
        LDSM4T(b[0][0], b[0][1], b[1][0], b[1][1], vAddr + ks*(16*QSTR*2));       // d0-15
        LDSM4T(b[2][0], b[2][1], b[3][0], b[3][1], vAddr + ks*(16*QSTR*2) + 32);  // d16-31
        #pragma unroll
        for (int nt = 0; nt < 4; ++nt)
            mma_bf16(acc2[nt], a, b[nt]);
    }

    // write O rows < 49 as bf16
    #pragma unroll
    for (int nt = 0; nt < 4; ++nt) {
        const int col = h*HDIM + nt*8 + 2*laneK;
        if (r0 < LW)
            *reinterpret_cast<uint32_t*>(&g_attn[(size_t)(w*LW + r0)*CCH + col]) =
                pack_bf16x2(acc2[nt][0], acc2[nt][1]);
        if (r1 < LW)
            *reinterpret_cast<uint32_t*>(&g_attn[(size_t)(w*LW + r1)*CCH + col]) =
                pack_bf16x2(acc2[nt][2], acc2[nt][3]);
    }
}

// ---------------- launch ----------------
extern "C" void kernel_launch(void* const* d_in, const int* in_sizes, int n_in,
                              void* d_out, int out_size)
{
    const void* arr[20];
    int na = 0;
    for (int i = 0; i < n_in && na < 20; ++i)
        if (in_sizes[i] != 1) arr[na++] = d_in[i];
    const float* x     = (const float*)arr[0];
    const float* n1w   = (const float*)arr[3];
    const float* n1b   = (const float*)arr[4];
    const float* qkvw  = (const float*)arr[5];
    const float* relb  = (const float*)arr[6];
    const float* projw = (const float*)arr[7];
    const float* projb = (const float*)arr[8];
    const float* n2w   = (const float*)arr[9];
    const float* n2b   = (const float*)arr[10];
    const float* fc1w  = (const float*)arr[11];
    const float* fc1b  = (const float*)arr[12];
    const float* fc2w  = (const float*)arr[13];
    const float* fc2b  = (const float*)arr[14];
    float* out = (float*)d_out;

    __nv_bfloat16 *p_ln1, *p_ln2, *p_qkv, *p_attn, *p_h1, *p_wb;
    cudaGetSymbolAddress((void**)&p_ln1,  g_ln1);
    cudaGetSymbolAddress((void**)&p_ln2,  g_ln2);
    cudaGetSymbolAddress((void**)&p_qkv,  g_qkv);
    cudaGetSymbolAddress((void**)&p_attn, g_attn);
    cudaGetSymbolAddress((void**)&p_h1,   g_h1);
    cudaGetSymbolAddress((void**)&p_wb,   g_wb);
    float* p_xres; cudaGetSymbolAddress((void**)&p_xres, g_xres);

    wconv_kernel<<<(WB_TOT/4 + 255)/256, 256>>>(qkvw, projw, fc1w, fc2w);
    btab_kernel<<<(4*NHEAD*LW*LW + 255)/256, 256>>>(relb);

    ln_norm_kernel<<<MTOK/8, 256>>>(x, n1w, n1b, p_ln1);

    gemm_tc<0, false, false, true, false, true><<<dim3(576/64, MTOK/128), 256>>>(
        p_ln1, p_wb + WB_QKV, nullptr, nullptr, p_qkv, MTOK, 3*CCH, CCH);

    attn_kernel<<<dim3(NHEAD, NWTOT), 128>>>();

    gemm_tc<0, true, false, false, true, false><<<dim3(192/64, MTOK/128), 256>>>(
        p_attn, p_wb + WB_PROJ, projb, x, p_xres, MTOK, CCH, CCH);

    ln_norm_kernel<<<MTOK/8, 256>>>(p_xres, n2w, n2b, p_ln2);

    gemm_tc<1, true, false, false, false, true><<<dim3(768/64, MTOK/128), 256>>>(
        p_ln2, p_wb + WB_FC1, fc1b, nullptr, p_h1, MTOK, 4*CCH, CCH);

    gemm_tc<1, true, true, false, false, false><<<dim3(192/64, MTOK/128), 256>>>(
        p_h1, p_wb + WB_FC2, fc2b, p_xres, out, MTOK, CCH, 4*CCH);

    (void)out_size;
}

// round 14
// speedup vs baseline: 1.9849x; 1.0548x over previous
#include <cuda_runtime.h>
#include <cuda_bf16.h>
#include <math.h>
#include <stdint.h>

// ---------------- static problem shape ----------------
#define BATCH 32
#define IMGH  56
#define IMGW  56
#define CCH   192
#define LLEN  (IMGH*IMGW)        // 3136
#define NHEAD 6
#define HDIM  32
#define WSZ   7
#define SHIFT_ 3
#define LW    49
#define NWIN  64
#define NWTOT (BATCH*NWIN)       // 2048
#define MTOK  (BATCH*LLEN)       // 100352
#define QKSCALE 13.856406460551018f

// bf16 weight buffer offsets (elements)
#define WB_QKV  0
#define WB_PROJ (WB_QKV + 3*CCH*CCH)
#define WB_FC1  (WB_PROJ + CCH*CCH)
#define WB_FC2  (WB_FC1 + 4*CCH*CCH)
#define WB_TOT  (WB_FC2 + 4*CCH*CCH)

// ---------------- scratch ----------------
__device__ __nv_bfloat16 g_ln1 [(size_t)MTOK*CCH];
__device__ __nv_bfloat16 g_ln2 [(size_t)MTOK*CCH];
__device__ __nv_bfloat16 g_qkv [(size_t)MTOK*3*CCH];
__device__ __nv_bfloat16 g_attn[(size_t)MTOK*CCH];
__device__ __nv_bfloat16 g_h1  [(size_t)MTOK*4*CCH];
__device__ __nv_bfloat16 g_wb  [WB_TOT];
__device__ float g_xres[(size_t)MTOK*CCH];
__device__ float g_btab[4*NHEAD*LW*LW];

__device__ __forceinline__ float gelu_exact(float x) {
    return 0.5f * x * (1.0f + erff(x * 0.70710678118654752f));
}
__device__ __forceinline__ uint32_t pack_bf16x2(float lo, float hi) {
    uint32_t o;
    asm("cvt.rn.bf16x2.f32 %0, %1, %2;" : "=r"(o) : "f"(hi), "f"(lo));
    return o;
}
__device__ __forceinline__ void mma_bf16(float c[4], const uint32_t a[4], const uint32_t b[2]) {
    asm volatile(
        "mma.sync.aligned.m16n8k16.row.col.f32.bf16.bf16.f32 "
        "{%0,%1,%2,%3}, {%4,%5,%6,%7}, {%8,%9}, {%0,%1,%2,%3};"
        : "+f"(c[0]), "+f"(c[1]), "+f"(c[2]), "+f"(c[3])
        : "r"(a[0]), "r"(a[1]), "r"(a[2]), "r"(a[3]), "r"(b[0]), "r"(b[1]));
}
#define LDSM4(r0, r1, r2, r3, addr)                                            \
    asm volatile("ldmatrix.sync.aligned.m8n8.x4.shared.b16 {%0,%1,%2,%3}, [%4];" \
                 : "=r"(r0), "=r"(r1), "=r"(r2), "=r"(r3) : "r"(addr))
#define LDSM4T(r0, r1, r2, r3, addr)                                           \
    asm volatile("ldmatrix.sync.aligned.m8n8.x4.trans.shared.b16 {%0,%1,%2,%3}, [%4];" \
                 : "=r"(r0), "=r"(r1), "=r"(r2), "=r"(r3) : "r"(addr))
__device__ __forceinline__ void cp_async16(uint32_t smem_addr, const void* gptr) {
    asm volatile("cp.async.cg.shared.global [%0], [%1], 16;" :: "r"(smem_addr), "l"(gptr));
}
__device__ __forceinline__ void cp_commit() { asm volatile("cp.async.commit_group;"); }
template<int N_> __device__ __forceinline__ void cp_wait() {
    asm volatile("cp.async.wait_group %0;" :: "n"(N_));
}

__device__ __forceinline__ int winrow_to_token(int wr) {
    const int w  = wr / LW, local = wr % LW;
    const int b  = w >> 6, wl = w & 63;
    const int hp = (wl >> 3)*WSZ + local/WSZ;
    const int wp = (wl & 7)*WSZ + local%WSZ;
    int h = hp + SHIFT_; if (h >= IMGH) h -= IMGH;
    int ww = wp + SHIFT_; if (ww >= IMGW) ww -= IMGW;
    return b*LLEN + h*IMGW + ww;
}
__device__ __forceinline__ int regid(int p) { return (p < 49) ? 0 : ((p < 53) ? 1 : 2); }

// ---------------- bias+mask table (once per launch) ----------------
__global__ void __launch_bounds__(256)
btab_kernel(const float* __restrict__ rel_bias)
{
    const int idx = blockIdx.x*256 + threadIdx.x;
    if (idx >= 4*NHEAD*LW*LW) return;
    const int j = idx % LW;
    const int i = (idx / LW) % LW;
    const int h = (idx / (LW*LW)) % NHEAD;
    const int p = idx / (NHEAD*LW*LW);
    const int wh = (p >> 1) ? 7 : 0;
    const int ww = (p & 1) ? 7 : 0;
    const int ih = i / WSZ, iw = i % WSZ;
    const int jh = j / WSZ, jw = j % WSZ;
    const int idi = regid(wh*WSZ + ih)*3 + regid(ww*WSZ + iw);
    const int idj = regid(wh*WSZ + jh)*3 + regid(ww*WSZ + jw);
    float v;
    if (idi != idj) v = -10000.0f;
    else            v = rel_bias[((ih - jh + 6)*13 + (iw - jw + 6))*NHEAD + h];
    g_btab[idx] = v;
}

// ---------------- weight fp32 -> bf16 conversion ----------------
__global__ void __launch_bounds__(256)
wconv_kernel(const float* __restrict__ w0, const float* __restrict__ w1,
             const float* __restrict__ w2, const float* __restrict__ w3)
{
    const int i = blockIdx.x*256 + threadIdx.x;
    const int n0 = 3*CCH*CCH/4, n1 = CCH*CCH/4, n2 = CCH*CCH;
    const float* src; int local; size_t off;
    if (i < n0)                { src = w0; local = i;            off = WB_QKV; }
    else if (i < n0+n1)        { src = w1; local = i - n0;       off = WB_PROJ; }
    else if (i < n0+n1+n2)     { src = w2; local = i - n0 - n1;  off = WB_FC1; }
    else if (i < n0+n1+2*n2)   { src = w3; local = i - n0-n1-n2; off = WB_FC2; }
    else return;
    const float4 v = reinterpret_cast<const float4*>(src)[local];
    uint2 o;
    o.x = pack_bf16x2(v.x, v.y);
    o.y = pack_bf16x2(v.z, v.w);
    *reinterpret_cast<uint2*>(&g_wb[off + (size_t)local*4]) = o;
}

// ---------------- LayerNorm: stats + normalize + bf16 store ----------------
__global__ void __launch_bounds__(256)
ln_norm_kernel(const float* __restrict__ in,
               const float* __restrict__ gamma, const float* __restrict__ beta,
               __nv_bfloat16* __restrict__ out)
{
    const int tok  = blockIdx.x*8 + (threadIdx.x >> 5);
    const int lane = threadIdx.x & 31;
    const float* p = in + (size_t)tok*CCH;

    float2 v[3];
    float s = 0.f, s2 = 0.f;
    #pragma unroll
    for (int i = 0; i < 3; ++i) {
        v[i] = *reinterpret_cast<const float2*>(&p[2*lane + 64*i]);
        s  += v[i].x + v[i].y;
        s2 += v[i].x*v[i].x + v[i].y*v[i].y;
    }
    #pragma unroll
    for (int off = 16; off > 0; off >>= 1) {
        s  += __shfl_xor_sync(0xffffffff, s,  off);
        s2 += __shfl_xor_sync(0xffffffff, s2, off);
    }
    const float mean = s * (1.0f/CCH);
    const float rstd = rsqrtf(s2 * (1.0f/CCH) - mean*mean + 1e-5f);

    #pragma unroll
    for (int i = 0; i < 3; ++i) {
        const float2 g = *reinterpret_cast<const float2*>(&gamma[2*lane + 64*i]);
        const float2 b = *reinterpret_cast<const float2*>(&beta [2*lane + 64*i]);
        const float y0 = (v[i].x - mean)*rstd*g.x + b.x;
        const float y1 = (v[i].y - mean)*rstd*g.y + b.y;
        *reinterpret_cast<uint32_t*>(&out[(size_t)tok*CCH + 2*lane + 64*i]) = pack_bf16x2(y0, y1);
    }
}

// ---------------- BF16 TC GEMM: BM=128, BN=64, BK=64, 2-stage cp.async + ldmatrix ----
// RS2=36 words/row (32 data + 4 pad): 16B-aligned chunks, LDSM conflict-free.
// 2 stages x (A 18.4KB + B 9.2KB) = 55.3KB dynamic smem; 4 CTAs/SM (221KB < 228KB).
#define RS2 36
#define ABUF2 (128*RS2)
#define BBUF2 (64*RS2)
#define GT_DSMEM (2*(ABUF2+BBUF2)*4)    // 55296 bytes
template<int ACT, bool HAS_BIAS, bool HAS_RES, bool GATHER, bool SCATTER, bool O_BF>
__global__ void __launch_bounds__(256, 4)
gemm_tc(const __nv_bfloat16* __restrict__ A, const __nv_bfloat16* __restrict__ B,
        const float* __restrict__ bias, const float* __restrict__ res,
        void* __restrict__ outv, int M, int N, int K)
{
    float* outf = (float*)outv;
    __nv_bfloat16* outb = (__nv_bfloat16*)outv;

    extern __shared__ uint32_t smem_dyn[];
    uint32_t* sA = smem_dyn;               // 2 stages of ABUF2
    uint32_t* sB = smem_dyn + 2*ABUF2;     // 2 stages of BBUF2

    const int tid  = threadIdx.x;
    const int lane = tid & 31;
    const int warp = tid >> 5;
    const int warpM = warp & 3;
    const int warpN = warp >> 2;
    const int m0 = blockIdx.y * 128;
    const int n0 = blockIdx.x * 64;

    float acc[2][4][4];
    #pragma unroll
    for (int i = 0; i < 2; ++i)
        #pragma unroll
        for (int j = 0; j < 4; ++j)
            #pragma unroll
            for (int q = 0; q < 4; ++q) acc[i][j][q] = 0.f;

    // cp.async mapping for BK=64: 8 x 16B chunks per row.
    // A: 128 rows -> 1024 chunks -> 4/thread (rows tid>>3, +32 each rep)
    // B: 64 rows  -> 512 chunks  -> 2/thread
    const int cRow  = tid >> 3;            // 0..31
    const int chunk = tid & 7;             // 0..7
    int aSrc[4];
    #pragma unroll
    for (int r = 0; r < 4; ++r)
        aSrc[r] = GATHER ? winrow_to_token(m0 + cRow + r*32) : m0 + cRow + r*32;

    const uint32_t saB = (uint32_t)__cvta_generic_to_shared(&sA[cRow*RS2 + chunk*4]);
    const uint32_t sbB = (uint32_t)__cvta_generic_to_shared(&sB[cRow*RS2 + chunk*4]);
    const __nv_bfloat16* pb = &B[(size_t)(n0 + cRow)*K + chunk*8];

    #define ISSUE(s, k0)                                                       \
    {                                                                          \
        _Pragma("unroll")                                                      \
        for (int r = 0; r < 4; ++r)                                            \
            cp_async16(saB + (s)*(ABUF2*4) + r*(32*RS2*4),                     \
                       &A[(size_t)aSrc[r]*K + (k0) + chunk*8]);                \
        cp_async16(sbB + (s)*(BBUF2*4),              pb + (k0));               \
        cp_async16(sbB + (s)*(BBUF2*4) + 32*RS2*4,   pb + (size_t)32*K + (k0));\
        cp_commit();                                                           \
    }

    ISSUE(0, 0)

    const uint32_t aLdsm = (uint32_t)__cvta_generic_to_shared(
        &sA[(warpM*32 + (lane & 7) + ((lane >> 3) & 1)*8)*RS2 + ((lane >> 4) & 1)*4]);
    const uint32_t bLdsm = (uint32_t)__cvta_generic_to_shared(
        &sB[(warpN*32 + (lane & 7) + ((lane >> 4) & 1)*8)*RS2 + ((lane >> 3) & 1)*4]);

    const int ntiles = K >> 6;
    for (int t = 0; t < ntiles; ++t) {
        cp_wait<0>();
        __syncthreads();
        if (t + 1 < ntiles) ISSUE((t + 1) & 1, (t + 1)*64)

        const int st = t & 1;
        const uint32_t aOff = aLdsm + st*(ABUF2*4);
        const uint32_t bOff = bLdsm + st*(BBUF2*4);
        #pragma unroll
        for (int ks = 0; ks < 4; ++ks) {
            uint32_t af[2][4], bf[4][2];
            LDSM4(af[0][0], af[0][1], af[0][2], af[0][3], aOff + ks*32);
            LDSM4(af[1][0], af[1][1], af[1][2], af[1][3], aOff + 16*RS2*4 + ks*32);
            LDSM4(bf[0][0], bf[0][1], bf[1][0], bf[1][1], bOff + ks*32);
            LDSM4(bf[2][0], bf[2][1], bf[3][0], bf[3][1], bOff + 16*RS2*4 + ks*32);
            #pragma unroll
            for (int mt = 0; mt < 2; ++mt)
                #pragma unroll
                for (int nt = 0; nt < 4; ++nt)
                    mma_bf16(acc[mt][nt], af[mt], bf[nt]);
        }
    }
    #undef ISSUE

    const int laneR = lane >> 2;
    const int laneK = lane & 3;
    #pragma unroll
    for (int mt = 0; mt < 2; ++mt) {
        #pragma unroll
        for (int nt = 0; nt < 4; ++nt) {
            const int col = n0 + warpN*32 + nt*8 + (laneK << 1);
            const float b0 = HAS_BIAS ? bias[col]   : 0.f;
            const float b1 = HAS_BIAS ? bias[col+1] : 0.f;
            #pragma unroll
            for (int half = 0; half < 2; ++half) {
                const int wr = m0 + warpM*32 + mt*16 + laneR + half*8;
                const int row = SCATTER ? winrow_to_token(wr) : wr;
                float v0 = acc[mt][nt][half*2+0] + b0;
                float v1 = acc[mt][nt][half*2+1] + b1;
                if (ACT == 1) { v0 = gelu_exact(v0); v1 = gelu_exact(v1); }
                if (HAS_RES || SCATTER) {
                    const float2 r2 = *reinterpret_cast<const float2*>(&res[(size_t)row*N + col]);
                    v0 += r2.x; v1 += r2.y;
                }
                if (O_BF) {
                    *reinterpret_cast<uint32_t*>(&outb[(size_t)row*N + col]) = pack_bf16x2(v0, v1);
                } else {
                    *reinterpret_cast<float2*>(&outf[(size_t)row*N + col]) = make_float2(v0, v1);
                }
            }
        }
    }
}

// ---------------- fused attention on tensor cores (mma.sync) ----------------
#define QSTR 40
#define PSTR 72
#define SSTRF 68

__global__ void __launch_bounds__(128)
attn_kernel()
{
    const int h = blockIdx.x;
    const int w = blockIdx.y;
    const int tid = threadIdx.x;
    const int lane = tid & 31;
    const int wi = tid >> 5;

    __shared__ __nv_bfloat16 sQ[64*QSTR];
    __shared__ __nv_bfloat16 sK[64*QSTR];
    __shared__ __nv_bfloat16 sV[64*QSTR];
    __shared__ float sS[LW*SSTRF];
    __shared__ __nv_bfloat16 sP[64*PSTR];

    for (int t = tid; t < LW*4; t += 128) {
        const int i = t >> 2, blk = (t & 3) << 3;
        const size_t base = (size_t)(w*LW + i)*(3*CCH) + h*HDIM + blk;
        *reinterpret_cast<uint4*>(&sQ[i*QSTR + blk]) = *reinterpret_cast<const uint4*>(&g_qkv[base]);
        *reinterpret_cast<uint4*>(&sK[i*QSTR + blk]) = *reinterpret_cast<const uint4*>(&g_qkv[base + CCH]);
        *reinterpret_cast<uint4*>(&sV[i*QSTR + blk]) = *reinterpret_cast<const uint4*>(&g_qkv[base + 2*CCH]);
    }
    for (int t = tid; t < 15*QSTR/2; t += 128)
        reinterpret_cast<uint32_t*>(&sV[49*QSTR])[t] = 0;
    __syncthreads();

    const int mB = wi*16;
    const int laneR = lane >> 2, laneK = lane & 3;
    const int r0 = mB + laneR, r1 = r0 + 8;

    float acc[8][4];
    #pragma unroll
    for (int i = 0; i < 8; ++i)
        #pragma unroll
        for (int q = 0; q < 4; ++q) acc[i][q] = 0.f;

    const uint32_t aAddr = (uint32_t)__cvta_generic_to_shared(
        &sQ[(mB + (lane & 7) + ((lane >> 3) & 1)*8)*QSTR + ((lane >> 4) & 1)*8]);
    const uint32_t kAddr = (uint32_t)__cvta_generic_to_shared(
        &sK[((lane & 7) + ((lane >> 4) & 1)*8)*QSTR + ((lane >> 3) & 1)*8]);

    #pragma unroll
    for (int ks = 0; ks < 2; ++ks) {
        uint32_t a[4];
        LDSM4(a[0], a[1], a[2], a[3], aAddr + ks*32);
        #pragma unroll
        for (int nb = 0; nb < 4; ++nb) {
            uint32_t b0[2], b1[2];
            LDSM4(b0[0], b0[1], b1[0], b1[1], kAddr + nb*(16*QSTR*2) + ks*32);
            mma_bf16(acc[nb*2+0], a, b0);
            mma_bf16(acc[nb*2+1], a, b1);
        }
    }

    {
        const int wl = w & (NWIN-1);
        const int pat = (((wl >> 3) == 7) ? 2 : 0) + (((wl & 7) == 7) ? 1 : 0);
        const float* bt = g_btab + (size_t)(pat*NHEAD + h)*LW*LW;
        #pragma unroll
        for (int nt = 0; nt < 8; ++nt) {
            const int c0 = nt*8 + 2*laneK;
            if (r0 < LW) {
                sS[r0*SSTRF + c0]   = (c0   < LW) ? acc[nt][0]*QKSCALE + bt[r0*LW + c0]   : -10000.f;
                sS[r0*SSTRF + c0+1] = (c0+1 < LW) ? acc[nt][1]*QKSCALE + bt[r0*LW + c0+1] : -10000.f;
            }
            if (r1 < LW) {
                sS[r1*SSTRF + c0]   = (c0   < LW) ? acc[nt][2]*QKSCALE + bt[r1*LW + c0]   : -10000.f;
                sS[r1*SSTRF + c0+1] = (c0+1 < LW) ? acc[nt][3]*QKSCALE + bt[r1*LW + c0+1] : -10000.f;
            }
        }
    }
    __syncthreads();

    if (tid < LW) {
        float* row = &sS[tid*SSTRF];
        float mx = -1e30f;
        #pragma unroll
        for (int j = 0; j < 64; ++j) mx = fmaxf(mx, row[j]);
        float sum = 0.f;
        #pragma unroll
        for (int j = 0; j < 64; ++j) {
            const float e = __expf(row[j] - mx);
            row[j] = e;
            sum += e;
        }
        const float inv = 1.0f / sum;
        uint32_t* prow = reinterpret_cast<uint32_t*>(&sP[tid*PSTR]);
        #pragma unroll
        for (int j = 0; j < 32; ++j)
            prow[j] = pack_bf16x2(row[2*j]*inv, row[2*j+1]*inv);
    }
    __syncthreads();

    float acc2[4][4];
    #pragma unroll
    for (int i = 0; i < 4; ++i)
        #pragma unroll
        for (int q = 0; q < 4; ++q) acc2[i][q] = 0.f;

    const uint32_t pAddr = (uint32_t)__cvta_generic_to_shared(
        &sP[(mB + (lane & 7) + ((lane >> 3) & 1)*8)*PSTR + ((lane >> 4) & 1)*8]);
    const uint32_t vAddr = (uint32_t)__cvta_generic_to_shared(
        &sV[((lane & 7) + ((lane >> 3) & 1)*8)*QSTR + ((lane >> 4) & 1)*8]);

    #pragma unroll
    for (int ks = 0; ks < 4; ++ks) {
        uint32_t a[4];
        LDSM4(a[0], a[1], a[2], a[3], pAddr + ks*32);
        uint32_t b[4][2];
        LDSM4T(b[0][0], b[0][1], b[1][0], b[1][1], vAddr + ks*(16*QSTR*2));
        LDSM4T(b[2][0], b[2][1], b[3][0], b[3][1], vAddr + ks*(16*QSTR*2) + 32);
        #pragma unroll
        for (int nt = 0; nt < 4; ++nt)
            mma_bf16(acc2[nt], a, b[nt]);
    }

    #pragma unroll
    for (int nt = 0; nt < 4; ++nt) {
        const int col = h*HDIM + nt*8 + 2*laneK;
        if (r0 < LW)
            *reinterpret_cast<uint32_t*>(&g_attn[(size_t)(w*LW + r0)*CCH + col]) =
                pack_bf16x2(acc2[nt][0], acc2[nt][1]);
        if (r1 < LW)
            *reinterpret_cast<uint32_t*>(&g_attn[(size_t)(w*LW + r1)*CCH + col]) =
                pack_bf16x2(acc2[nt][2], acc2[nt][3]);
    }
}

// ---------------- launch ----------------
extern "C" void kernel_launch(void* const* d_in, const int* in_sizes, int n_in,
                              void* d_out, int out_size)
{
    const void* arr[20];
    int na = 0;
    for (int i = 0; i < n_in && na < 20; ++i)
        if (in_sizes[i] != 1) arr[na++] = d_in[i];
    const float* x     = (const float*)arr[0];
    const float* n1w   = (const float*)arr[3];
    const float* n1b   = (const float*)arr[4];
    const float* qkvw  = (const float*)arr[5];
    const float* relb  = (const float*)arr[6];
    const float* projw = (const float*)arr[7];
    const float* projb = (const float*)arr[8];
    const float* n2w   = (const float*)arr[9];
    const float* n2b   = (const float*)arr[10];
    const float* fc1w  = (const float*)arr[11];
    const float* fc1b  = (const float*)arr[12];
    const float* fc2w  = (const float*)arr[13];
    const float* fc2b  = (const float*)arr[14];
    float* out = (float*)d_out;

    __nv_bfloat16 *p_ln1, *p_ln2, *p_qkv, *p_attn, *p_h1, *p_wb;
    cudaGetSymbolAddress((void**)&p_ln1,  g_ln1);
    cudaGetSymbolAddress((void**)&p_ln2,  g_ln2);
    cudaGetSymbolAddress((void**)&p_qkv,  g_qkv);
    cudaGetSymbolAddress((void**)&p_attn, g_attn);
    cudaGetSymbolAddress((void**)&p_h1,   g_h1);
    cudaGetSymbolAddress((void**)&p_wb,   g_wb);
    float* p_xres; cudaGetSymbolAddress((void**)&p_xres, g_xres);

    static bool attr_done = false;
    if (!attr_done) {
        cudaFuncSetAttribute(gemm_tc<0, false, false, true,  false, true >,
                             cudaFuncAttributeMaxDynamicSharedMemorySize, GT_DSMEM);
        cudaFuncSetAttribute(gemm_tc<0, true,  false, false, true,  false>,
                             cudaFuncAttributeMaxDynamicSharedMemorySize, GT_DSMEM);
        cudaFuncSetAttribute(gemm_tc<1, true,  false, false, false, true >,
                             cudaFuncAttributeMaxDynamicSharedMemorySize, GT_DSMEM);
        cudaFuncSetAttribute(gemm_tc<1, true,  true,  false, false, false>,
                             cudaFuncAttributeMaxDynamicSharedMemorySize, GT_DSMEM);
        attr_done = true;
    }

    wconv_kernel<<<(WB_TOT/4 + 255)/256, 256>>>(qkvw, projw, fc1w, fc2w);
    btab_kernel<<<(4*NHEAD*LW*LW + 255)/256, 256>>>(relb);

    ln_norm_kernel<<<MTOK/8, 256>>>(x, n1w, n1b, p_ln1);

    gemm_tc<0, false, false, true, false, true><<<dim3(576/64, MTOK/128), 256, GT_DSMEM>>>(
        p_ln1, p_wb + WB_QKV, nullptr, nullptr, p_qkv, MTOK, 3*CCH, CCH);

    attn_kernel<<<dim3(NHEAD, NWTOT), 128>>>();

    gemm_tc<0, true, false, false, true, false><<<dim3(192/64, MTOK/128), 256, GT_DSMEM>>>(
        p_attn, p_wb + WB_PROJ, projb, x, p_xres, MTOK, CCH, CCH);

    ln_norm_kernel<<<MTOK/8, 256>>>(p_xres, n2w, n2b, p_ln2);

    gemm_tc<1, true, false, false, false, true><<<dim3(768/64, MTOK/128), 256, GT_DSMEM>>>(
        p_ln2, p_wb + WB_FC1, fc1b, nullptr, p_h1, MTOK, 4*CCH, CCH);

    gemm_tc<1, true, true, false, false, false><<<dim3(192/64, MTOK/128), 256, GT_DSMEM>>>(
        p_h1, p_wb + WB_FC2, fc2b, p_xres, out, MTOK, CCH, 4*CCH);

    (void)out_size;
}

// round 15
// speedup vs baseline: 2.0770x; 1.0464x over previous
#include <cuda_runtime.h>
#include <cuda_bf16.h>
#include <math.h>
#include <stdint.h>

// ---------------- static problem shape ----------------
#define BATCH 32
#define IMGH  56
#define IMGW  56
#define CCH   192
#define LLEN  (IMGH*IMGW)        // 3136
#define NHEAD 6
#define HDIM  32
#define WSZ   7
#define SHIFT_ 3
#define LW    49
#define NWIN  64
#define NWTOT (BATCH*NWIN)       // 2048
#define MTOK  (BATCH*LLEN)       // 100352
#define QKSCALE 13.856406460551018f

// bf16 weight buffer offsets (elements)
#define WB_QKV  0
#define WB_PROJ (WB_QKV + 3*CCH*CCH)
#define WB_FC1  (WB_PROJ + CCH*CCH)
#define WB_FC2  (WB_FC1 + 4*CCH*CCH)
#define WB_TOT  (WB_FC2 + 4*CCH*CCH)

// ---------------- scratch ----------------
__device__ __nv_bfloat16 g_ln1 [(size_t)MTOK*CCH];
__device__ __nv_bfloat16 g_ln2 [(size_t)MTOK*CCH];
__device__ __nv_bfloat16 g_qkv [(size_t)MTOK*3*CCH];
__device__ __nv_bfloat16 g_attn[(size_t)MTOK*CCH];
__device__ __nv_bfloat16 g_h1  [(size_t)MTOK*4*CCH];
__device__ __nv_bfloat16 g_wb  [WB_TOT];
__device__ float g_xres[(size_t)MTOK*CCH];
__device__ float g_btab[4*NHEAD*LW*LW];

__device__ __forceinline__ float gelu_exact(float x) {
    return 0.5f * x * (1.0f + erff(x * 0.70710678118654752f));
}
__device__ __forceinline__ uint32_t pack_bf16x2(float lo, float hi) {
    uint32_t o;
    asm("cvt.rn.bf16x2.f32 %0, %1, %2;" : "=r"(o) : "f"(hi), "f"(lo));
    return o;
}
__device__ __forceinline__ void mma_bf16(float c[4], const uint32_t a[4], const uint32_t b[2]) {
    asm volatile(
        "mma.sync.aligned.m16n8k16.row.col.f32.bf16.bf16.f32 "
        "{%0,%1,%2,%3}, {%4,%5,%6,%7}, {%8,%9}, {%0,%1,%2,%3};"
        : "+f"(c[0]), "+f"(c[1]), "+f"(c[2]), "+f"(c[3])
        : "r"(a[0]), "r"(a[1]), "r"(a[2]), "r"(a[3]), "r"(b[0]), "r"(b[1]));
}
#define LDSM4(r0, r1, r2, r3, addr)                                            \
    asm volatile("ldmatrix.sync.aligned.m8n8.x4.shared.b16 {%0,%1,%2,%3}, [%4];" \
                 : "=r"(r0), "=r"(r1), "=r"(r2), "=r"(r3) : "r"(addr))
#define LDSM4T(r0, r1, r2, r3, addr)                                           \
    asm volatile("ldmatrix.sync.aligned.m8n8.x4.trans.shared.b16 {%0,%1,%2,%3}, [%4];" \
                 : "=r"(r0), "=r"(r1), "=r"(r2), "=r"(r3) : "r"(addr))
__device__ __forceinline__ void cp_async16(uint32_t smem_addr, const void* gptr) {
    asm volatile("cp.async.cg.shared.global [%0], [%1], 16;" :: "r"(smem_addr), "l"(gptr));
}
__device__ __forceinline__ void cp_commit() { asm volatile("cp.async.commit_group;"); }
template<int N_> __device__ __forceinline__ void cp_wait() {
    asm volatile("cp.async.wait_group %0;" :: "n"(N_));
}

__device__ __forceinline__ int winrow_to_token(int wr) {
    const int w  = wr / LW, local = wr % LW;
    const int b  = w >> 6, wl = w & 63;
    const int hp = (wl >> 3)*WSZ + local/WSZ;
    const int wp = (wl & 7)*WSZ + local%WSZ;
    int h = hp + SHIFT_; if (h >= IMGH) h -= IMGH;
    int ww = wp + SHIFT_; if (ww >= IMGW) ww -= IMGW;
    return b*LLEN + h*IMGW + ww;
}
__device__ __forceinline__ int regid(int p) { return (p < 49) ? 0 : ((p < 53) ? 1 : 2); }

// ---------------- bias+mask table (once per launch) ----------------
__global__ void __launch_bounds__(256)
btab_kernel(const float* __restrict__ rel_bias)
{
    const int idx = blockIdx.x*256 + threadIdx.x;
    if (idx >= 4*NHEAD*LW*LW) return;
    const int j = idx % LW;
    const int i = (idx / LW) % LW;
    const int h = (idx / (LW*LW)) % NHEAD;
    const int p = idx / (NHEAD*LW*LW);
    const int wh = (p >> 1) ? 7 : 0;
    const int ww = (p & 1) ? 7 : 0;
    const int ih = i / WSZ, iw = i % WSZ;
    const int jh = j / WSZ, jw = j % WSZ;
    const int idi = regid(wh*WSZ + ih)*3 + regid(ww*WSZ + iw);
    const int idj = regid(wh*WSZ + jh)*3 + regid(ww*WSZ + jw);
    float v;
    if (idi != idj) v = -10000.0f;
    else            v = rel_bias[((ih - jh + 6)*13 + (iw - jw + 6))*NHEAD + h];
    g_btab[idx] = v;
}

// ---------------- weight fp32 -> bf16 conversion ----------------
__global__ void __launch_bounds__(256)
wconv_kernel(const float* __restrict__ w0, const float* __restrict__ w1,
             const float* __restrict__ w2, const float* __restrict__ w3)
{
    const int i = blockIdx.x*256 + threadIdx.x;
    const int n0 = 3*CCH*CCH/4, n1 = CCH*CCH/4, n2 = CCH*CCH;
    const float* src; int local; size_t off;
    if (i < n0)                { src = w0; local = i;            off = WB_QKV; }
    else if (i < n0+n1)        { src = w1; local = i - n0;       off = WB_PROJ; }
    else if (i < n0+n1+n2)     { src = w2; local = i - n0 - n1;  off = WB_FC1; }
    else if (i < n0+n1+2*n2)   { src = w3; local = i - n0-n1-n2; off = WB_FC2; }
    else return;
    const float4 v = reinterpret_cast<const float4*>(src)[local];
    uint2 o;
    o.x = pack_bf16x2(v.x, v.y);
    o.y = pack_bf16x2(v.z, v.w);
    *reinterpret_cast<uint2*>(&g_wb[off + (size_t)local*4]) = o;
}

// ---------------- LayerNorm: stats + normalize + bf16 store ----------------
__global__ void __launch_bounds__(256)
ln_norm_kernel(const float* __restrict__ in,
               const float* __restrict__ gamma, const float* __restrict__ beta,
               __nv_bfloat16* __restrict__ out)
{
    const int tok  = blockIdx.x*8 + (threadIdx.x >> 5);
    const int lane = threadIdx.x & 31;
    const float* p = in + (size_t)tok*CCH;

    float2 v[3];
    float s = 0.f, s2 = 0.f;
    #pragma unroll
    for (int i = 0; i < 3; ++i) {
        v[i] = *reinterpret_cast<const float2*>(&p[2*lane + 64*i]);
        s  += v[i].x + v[i].y;
        s2 += v[i].x*v[i].x + v[i].y*v[i].y;
    }
    #pragma unroll
    for (int off = 16; off > 0; off >>= 1) {
        s  += __shfl_xor_sync(0xffffffff, s,  off);
        s2 += __shfl_xor_sync(0xffffffff, s2, off);
    }
    const float mean = s * (1.0f/CCH);
    const float rstd = rsqrtf(s2 * (1.0f/CCH) - mean*mean + 1e-5f);

    #pragma unroll
    for (int i = 0; i < 3; ++i) {
        const float2 g = *reinterpret_cast<const float2*>(&gamma[2*lane + 64*i]);
        const float2 b = *reinterpret_cast<const float2*>(&beta [2*lane + 64*i]);
        const float y0 = (v[i].x - mean)*rstd*g.x + b.x;
        const float y1 = (v[i].y - mean)*rstd*g.y + b.y;
        *reinterpret_cast<uint32_t*>(&out[(size_t)tok*CCH + 2*lane + 64*i]) = pack_bf16x2(y0, y1);
    }
}

// ---------------- BF16 TC GEMM: BM=128, BN=64, BK=64; 128 threads, 4 warps 2Mx2N,
// warp tile 64x32. 2-stage cp.async + ldmatrix. 4 CTAs/SM.
#define RS2 36
#define ABUF2 (128*RS2)
#define BBUF2 (64*RS2)
#define GT_DSMEM (2*(ABUF2+BBUF2)*4)    // 55296 bytes
template<int ACT, bool HAS_BIAS, bool HAS_RES, bool GATHER, bool SCATTER, bool O_BF>
__global__ void __launch_bounds__(128, 4)
gemm_tc(const __nv_bfloat16* __restrict__ A, const __nv_bfloat16* __restrict__ B,
        const float* __restrict__ bias, const float* __restrict__ res,
        void* __restrict__ outv, int M, int N, int K)
{
    float* outf = (float*)outv;
    __nv_bfloat16* outb = (__nv_bfloat16*)outv;

    extern __shared__ uint32_t smem_dyn[];
    uint32_t* sA = smem_dyn;
    uint32_t* sB = smem_dyn + 2*ABUF2;

    const int tid  = threadIdx.x;
    const int lane = tid & 31;
    const int warp = tid >> 5;             // 0..3
    const int warpM = warp & 1;            // 64-row slab
    const int warpN = warp >> 1;           // 32-col slab
    const int m0 = blockIdx.y * 128;
    const int n0 = blockIdx.x * 64;

    float acc[4][4][4];                    // [m16 subtile][n8 subtile][frag]
    #pragma unroll
    for (int i = 0; i < 4; ++i)
        #pragma unroll
        for (int j = 0; j < 4; ++j)
            #pragma unroll
            for (int q = 0; q < 4; ++q) acc[i][j][q] = 0.f;

    // cp.async mapping: 8 chunks/row of 16B. 128 threads.
    // A: 128 rows -> 1024 chunks -> 8/thread (rows tid>>3 + r*16)
    // B: 64 rows  -> 512 chunks  -> 4/thread
    const int cRow  = tid >> 3;            // 0..15
    const int chunk = tid & 7;             // 0..7
    int aSrc[8];
    #pragma unroll
    for (int r = 0; r < 8; ++r)
        aSrc[r] = GATHER ? winrow_to_token(m0 + cRow + r*16) : m0 + cRow + r*16;

    const uint32_t saB = (uint32_t)__cvta_generic_to_shared(&sA[cRow*RS2 + chunk*4]);
    const uint32_t sbB = (uint32_t)__cvta_generic_to_shared(&sB[cRow*RS2 + chunk*4]);
    const __nv_bfloat16* pb = &B[(size_t)(n0 + cRow)*K + chunk*8];

    #define ISSUE(s, k0)                                                       \
    {                                                                          \
        _Pragma("unroll")                                                      \
        for (int r = 0; r < 8; ++r)                                            \
            cp_async16(saB + (s)*(ABUF2*4) + r*(16*RS2*4),                     \
                       &A[(size_t)aSrc[r]*K + (k0) + chunk*8]);                \
        _Pragma("unroll")                                                      \
        for (int r = 0; r < 4; ++r)                                            \
            cp_async16(sbB + (s)*(BBUF2*4) + r*(16*RS2*4),                     \
                       pb + (size_t)(r*16)*K + (k0));                          \
        cp_commit();                                                           \
    }

    ISSUE(0, 0)

    const uint32_t aLdsm = (uint32_t)__cvta_generic_to_shared(
        &sA[(warpM*64 + (lane & 7) + ((lane >> 3) & 1)*8)*RS2 + ((lane >> 4) & 1)*4]);
    const uint32_t bLdsm = (uint32_t)__cvta_generic_to_shared(
        &sB[(warpN*32 + (lane & 7) + ((lane >> 4) & 1)*8)*RS2 + ((lane >> 3) & 1)*4]);

    const int ntiles = K >> 6;
    for (int t = 0; t < ntiles; ++t) {
        cp_wait<0>();
        __syncthreads();
        if (t + 1 < ntiles) ISSUE((t + 1) & 1, (t + 1)*64)

        const int st = t & 1;
        const uint32_t aOff = aLdsm + st*(ABUF2*4);
        const uint32_t bOff = bLdsm + st*(BBUF2*4);
        #pragma unroll
        for (int ks = 0; ks < 4; ++ks) {
            uint32_t af[4][4], bf[4][2];
            #pragma unroll
            for (int mt = 0; mt < 4; ++mt)
                LDSM4(af[mt][0], af[mt][1], af[mt][2], af[mt][3],
                      aOff + mt*(16*RS2*4) + ks*32);
            LDSM4(bf[0][0], bf[0][1], bf[1][0], bf[1][1], bOff + ks*32);
            LDSM4(bf[2][0], bf[2][1], bf[3][0], bf[3][1], bOff + 16*RS2*4 + ks*32);
            #pragma unroll
            for (int mt = 0; mt < 4; ++mt)
                #pragma unroll
                for (int nt = 0; nt < 4; ++nt)
                    mma_bf16(acc[mt][nt], af[mt], bf[nt]);
        }
    }
    #undef ISSUE

    const int laneR = lane >> 2;
    const int laneK = lane & 3;
    #pragma unroll
    for (int mt = 0; mt < 4; ++mt) {
        #pragma unroll
        for (int nt = 0; nt < 4; ++nt) {
            const int col = n0 + warpN*32 + nt*8 + (laneK << 1);
            const float b0 = HAS_BIAS ? bias[col]   : 0.f;
            const float b1 = HAS_BIAS ? bias[col+1] : 0.f;
            #pragma unroll
            for (int half = 0; half < 2; ++half) {
                const int wr = m0 + warpM*64 + mt*16 + laneR + half*8;
                const int row = SCATTER ? winrow_to_token(wr) : wr;
                float v0 = acc[mt][nt][half*2+0] + b0;
                float v1 = acc[mt][nt][half*2+1] + b1;
                if (ACT == 1) { v0 = gelu_exact(v0); v1 = gelu_exact(v1); }
                if (HAS_RES || SCATTER) {
                    const float2 r2 = *reinterpret_cast<const float2*>(&res[(size_t)row*N + col]);
                    v0 += r2.x; v1 += r2.y;
                }
                if (O_BF) {
                    *reinterpret_cast<uint32_t*>(&outb[(size_t)row*N + col]) = pack_bf16x2(v0, v1);
                } else {
                    *reinterpret_cast<float2*>(&outf[(size_t)row*N + col]) = make_float2(v0, v1);
                }
            }
        }
    }
}

// ---------------- fused attention on tensor cores (mma.sync) ----------------
#define QSTR 40
#define PSTR 72
#define SSTRF 68

__global__ void __launch_bounds__(128)
attn_kernel()
{
    const int h = blockIdx.x;
    const int w = blockIdx.y;
    const int tid = threadIdx.x;
    const int lane = tid & 31;
    const int wi = tid >> 5;

    __shared__ __nv_bfloat16 sQ[64*QSTR];
    __shared__ __nv_bfloat16 sK[64*QSTR];
    __shared__ __nv_bfloat16 sV[64*QSTR];
    __shared__ float sS[LW*SSTRF];
    __shared__ __nv_bfloat16 sP[64*PSTR];

    for (int t = tid; t < LW*4; t += 128) {
        const int i = t >> 2, blk = (t & 3) << 3;
        const size_t base = (size_t)(w*LW + i)*(3*CCH) + h*HDIM + blk;
        *reinterpret_cast<uint4*>(&sQ[i*QSTR + blk]) = *reinterpret_cast<const uint4*>(&g_qkv[base]);
        *reinterpret_cast<uint4*>(&sK[i*QSTR + blk]) = *reinterpret_cast<const uint4*>(&g_qkv[base + CCH]);
        *reinterpret_cast<uint4*>(&sV[i*QSTR + blk]) = *reinterpret_cast<const uint4*>(&g_qkv[base + 2*CCH]);
    }
    for (int t = tid; t < 15*QSTR/2; t += 128)
        reinterpret_cast<uint32_t*>(&sV[49*QSTR])[t] = 0;
    __syncthreads();

    const int mB = wi*16;
    const int laneR = lane >> 2, laneK = lane & 3;
    const int r0 = mB + laneR, r1 = r0 + 8;

    float acc[8][4];
    #pragma unroll
    for (int i = 0; i < 8; ++i)
        #pragma unroll
        for (int q = 0; q < 4; ++q) acc[i][q] = 0.f;

    const uint32_t aAddr = (uint32_t)__cvta_generic_to_shared(
        &sQ[(mB + (lane & 7) + ((lane >> 3) & 1)*8)*QSTR + ((lane >> 4) & 1)*8]);
    const uint32_t kAddr = (uint32_t)__cvta_generic_to_shared(
        &sK[((lane & 7) + ((lane >> 4) & 1)*8)*QSTR + ((lane >> 3) & 1)*8]);

    #pragma unroll
    for (int ks = 0; ks < 2; ++ks) {
        uint32_t a[4];
        LDSM4(a[0], a[1], a[2], a[3], aAddr + ks*32);
        #pragma unroll
        for (int nb = 0; nb < 4; ++nb) {
            uint32_t b0[2], b1[2];
            LDSM4(b0[0], b0[1], b1[0], b1[1], kAddr + nb*(16*QSTR*2) + ks*32);
            mma_bf16(acc[nb*2+0], a, b0);
            mma_bf16(acc[nb*2+1], a, b1);
        }
    }

    {
        const int wl = w & (NWIN-1);
        const int pat = (((wl >> 3) == 7) ? 2 : 0) + (((wl & 7) == 7) ? 1 : 0);
        const float* bt = g_btab + (size_t)(pat*NHEAD + h)*LW*LW;
        #pragma unroll
        for (int nt = 0; nt < 8; ++nt) {
            const int c0 = nt*8 + 2*laneK;
            if (r0 < LW) {
                sS[r0*SSTRF + c0]   = (c0   < LW) ? acc[nt][0]*QKSCALE + bt[r0*LW + c0]   : -10000.f;
                sS[r0*SSTRF + c0+1] = (c0+1 < LW) ? acc[nt][1]*QKSCALE + bt[r0*LW + c0+1] : -10000.f;
            }
            if (r1 < LW) {
                sS[r1*SSTRF + c0]   = (c0   < LW) ? acc[nt][2]*QKSCALE + bt[r1*LW + c0]   : -10000.f;
                sS[r1*SSTRF + c0+1] = (c0+1 < LW) ? acc[nt][3]*QKSCALE + bt[r1*LW + c0+1] : -10000.f;
            }
        }
    }
    __syncthreads();

    if (tid < LW) {
        float* row = &sS[tid*SSTRF];
        float mx = -1e30f;
        #pragma unroll
        for (int j = 0; j < 64; ++j) mx = fmaxf(mx, row[j]);
        float sum = 0.f;
        #pragma unroll
        for (int j = 0; j < 64; ++j) {
            const float e = __expf(row[j] - mx);
            row[j] = e;
            sum += e;
        }
        const float inv = 1.0f / sum;
        uint32_t* prow = reinterpret_cast<uint32_t*>(&sP[tid*PSTR]);
        #pragma unroll
        for (int j = 0; j < 32; ++j)
            prow[j] = pack_bf16x2(row[2*j]*inv, row[2*j+1]*inv);
    }
    __syncthreads();

    float acc2[4][4];
    #pragma unroll
    for (int i = 0; i < 4; ++i)
        #pragma unroll
        for (int q = 0; q < 4; ++q) acc2[i][q] = 0.f;

    const uint32_t pAddr = (uint32_t)__cvta_generic_to_shared(
        &sP[(mB + (lane & 7) + ((lane >> 3) & 1)*8)*PSTR + ((lane >> 4) & 1)*8]);
    const uint32_t vAddr = (uint32_t)__cvta_generic_to_shared(
        &sV[((lane & 7) + ((lane >> 3) & 1)*8)*QSTR + ((lane >> 4) & 1)*8]);

    #pragma unroll
    for (int ks = 0; ks < 4; ++ks) {
        uint32_t a[4];
        LDSM4(a[0], a[1], a[2], a[3], pAddr + ks*32);
        uint32_t b[4][2];
        LDSM4T(b[0][0], b[0][1], b[1][0], b[1][1], vAddr + ks*(16*QSTR*2));
        LDSM4T(b[2][0], b[2][1], b[3][0], b[3][1], vAddr + ks*(16*QSTR*2) + 32);
        #pragma unroll
        for (int nt = 0; nt < 4; ++nt)
            mma_bf16(acc2[nt], a, b[nt]);
    }

    #pragma unroll
    for (int nt = 0; nt < 4; ++nt) {
        const int col = h*HDIM + nt*8 + 2*laneK;
        if (r0 < LW)
            *reinterpret_cast<uint32_t*>(&g_attn[(size_t)(w*LW + r0)*CCH + col]) =
                pack_bf16x2(acc2[nt][0], acc2[nt][1]);
        if (r1 < LW)
            *reinterpret_cast<uint32_t*>(&g_attn[(size_t)(w*LW + r1)*CCH + col]) =
                pack_bf16x2(acc2[nt][2], acc2[nt][3]);
    }
}

// ---------------- launch ----------------
extern "C" void kernel_launch(void* const* d_in, const int* in_sizes, int n_in,
                              void* d_out, int out_size)
{
    const void* arr[20];
    int na = 0;
    for (int i = 0; i < n_in && na < 20; ++i)
        if (in_sizes[i] != 1) arr[na++] = d_in[i];
    const float* x     = (const float*)arr[0];
    const float* n1w   = (const float*)arr[3];
    const float* n1b   = (const float*)arr[4];
    const float* qkvw  = (const float*)arr[5];
    const float* relb  = (const float*)arr[6];
    const float* projw = (const float*)arr[7];
    const float* projb = (const float*)arr[8];
    const float* n2w   = (const float*)arr[9];
    const float* n2b   = (const float*)arr[10];
    const float* fc1w  = (const float*)arr[11];
    const float* fc1b  = (const float*)arr[12];
    const float* fc2w  = (const float*)arr[13];
    const float* fc2b  = (const float*)arr[14];
    float* out = (float*)d_out;

    __nv_bfloat16 *p_ln1, *p_ln2, *p_qkv, *p_attn, *p_h1, *p_wb;
    cudaGetSymbolAddress((void**)&p_ln1,  g_ln1);
    cudaGetSymbolAddress((void**)&p_ln2,  g_ln2);
    cudaGetSymbolAddress((void**)&p_qkv,  g_qkv);
    cudaGetSymbolAddress((void**)&p_attn, g_attn);
    cudaGetSymbolAddress((void**)&p_h1,   g_h1);
    cudaGetSymbolAddress((void**)&p_wb,   g_wb);
    float* p_xres; cudaGetSymbolAddress((void**)&p_xres, g_xres);

    static bool attr_done = false;
    if (!attr_done) {
        cudaFuncSetAttribute(gemm_tc<0, false, false, true,  false, true >,
                             cudaFuncAttributeMaxDynamicSharedMemorySize, GT_DSMEM);
        cudaFuncSetAttribute(gemm_tc<0, true,  false, false, true,  false>,
                             cudaFuncAttributeMaxDynamicSharedMemorySize, GT_DSMEM);
        cudaFuncSetAttribute(gemm_tc<1, true,  false, false, false, true >,
                             cudaFuncAttributeMaxDynamicSharedMemorySize, GT_DSMEM);
        cudaFuncSetAttribute(gemm_tc<1, true,  true,  false, false, false>,
                             cudaFuncAttributeMaxDynamicSharedMemorySize, GT_DSMEM);
        attr_done = true;
    }

    wconv_kernel<<<(WB_TOT/4 + 255)/256, 256>>>(qkvw, projw, fc1w, fc2w);
    btab_kernel<<<(4*NHEAD*LW*LW + 255)/256, 256>>>(relb);

    ln_norm_kernel<<<MTOK/8, 256>>>(x, n1w, n1b, p_ln1);

    gemm_tc<0, false, false, true, false, true><<<dim3(576/64, MTOK/128), 128, GT_DSMEM>>>(
        p_ln1, p_wb + WB_QKV, nullptr, nullptr, p_qkv, MTOK, 3*CCH, CCH);

    attn_kernel<<<dim3(NHEAD, NWTOT), 128>>>();

    gemm_tc<0, true, false, false, true, false><<<dim3(192/64, MTOK/128), 128, GT_DSMEM>>>(
        p_attn, p_wb + WB_PROJ, projb, x, p_xres, MTOK, CCH, CCH);

    ln_norm_kernel<<<MTOK/8, 256>>>(p_xres, n2w, n2b, p_ln2);

    gemm_tc<1, true, false, false, false, true><<<dim3(768/64, MTOK/128), 128, GT_DSMEM>>>(
        p_ln2, p_wb + WB_FC1, fc1b, nullptr, p_h1, MTOK, 4*CCH, CCH);

    gemm_tc<1, true, true, false, false, false><<<dim3(192/64, MTOK/128), 128, GT_DSMEM>>>(
        p_h1, p_wb + WB_FC2, fc2b, p_xres, out, MTOK, CCH, 4*CCH);

    (void)out_size;
}